// round 1
// baseline (speedup 1.0000x reference)
#include <cuda_runtime.h>
#include <math.h>

#define S_LEN 2048
#define H_DIM 1024
#define NHEAD 16
#define HEADD 64
#define INNER_DIM 4096

// ---- scratch (static __device__ allowed; no cudaMalloc anywhere) ----
__device__ float g_x[S_LEN * H_DIM];                       // LN output, reused 3x
__device__ float g_qkv[S_LEN * 3 * H_DIM];                 // self-attn qkv
__device__ float g_scores[(size_t)NHEAD * S_LEN * S_LEN];  // 256MB score scratch, reused
__device__ float g_attn[S_LEN * H_DIM];                    // merged attention output
__device__ float g_hid2[S_LEN * H_DIM];                    // after self-attn residual
__device__ float g_hid3[S_LEN * H_DIM];                    // after cross-attn residual
__device__ float g_q[S_LEN * H_DIM];                       // cross-attn q
__device__ float g_kv[S_LEN * 2 * H_DIM];                  // cross-attn kv
__device__ float g_mlp[S_LEN * INNER_DIM];                 // MLP inner

__device__ __forceinline__ float gelu_new(float x) {
    const float c = 0.7978845608028654f;  // sqrt(2/pi)
    float t = tanhf(c * (x + 0.044715f * x * x * x));
    return 0.5f * x * (1.0f + t);
}

// ---------------------------------------------------------------------------
// LayerNorm: one block per row of H=1024, 256 threads, 4 elems/thread.
// ---------------------------------------------------------------------------
__global__ void ln_kernel(const float* __restrict__ X, const float* __restrict__ g,
                          const float* __restrict__ b, float* __restrict__ Y)
{
    const float* x = X + (long long)blockIdx.x * H_DIM;
    float* y = Y + (long long)blockIdx.x * H_DIM;
    int tid = threadIdx.x;

    float v[4];
    float s = 0.f, ss = 0.f;
#pragma unroll
    for (int i = 0; i < 4; i++) {
        v[i] = x[tid + i * 256];
        s += v[i];
        ss += v[i] * v[i];
    }
    __shared__ float r1[256], r2[256];
    r1[tid] = s; r2[tid] = ss;
    __syncthreads();
#pragma unroll
    for (int st = 128; st >= 1; st >>= 1) {
        if (tid < st) { r1[tid] += r1[tid + st]; r2[tid] += r2[tid + st]; }
        __syncthreads();
    }
    float mean = r1[0] * (1.0f / H_DIM);
    float var = r2[0] * (1.0f / H_DIM) - mean * mean;
    float inv = rsqrtf(var + 1e-5f);
#pragma unroll
    for (int i = 0; i < 4; i++) {
        int c = tid + i * 256;
        y[c] = (v[i] - mean) * inv * g[c] + b[c];
    }
}

// ---------------------------------------------------------------------------
// Generic tiled GEMM: C[M,N] = A[M,K] @ B[K,N] (+bias, +gelu, +residual).
// 64x64 tile, BK=16, 256 threads, 4x4 per thread. Batched via z strides.
// All dims are exact multiples of tile sizes for this problem -> no guards.
// ---------------------------------------------------------------------------
__global__ void gemm_kernel(const float* __restrict__ A, int lda, long long aBatch,
                            const float* __restrict__ B, int ldb, long long bBatch,
                            const float* __restrict__ bias,
                            const float* __restrict__ res, int ldres,
                            float* __restrict__ C, int ldc, long long cBatch,
                            int K, int act)
{
    __shared__ float As[64][17];   // [m][k], padded: conflict-free store + broadcast read
    __shared__ float Ws[16][64];   // [k][n], float4 reads

    long long z = blockIdx.z;
    A += z * aBatch; B += z * bBatch; C += z * cBatch;

    int m0 = blockIdx.y * 64;
    int n0 = blockIdx.x * 64;
    int tid = threadIdx.x;
    int tx = tid & 15, ty = tid >> 4;
    int tx4 = tx * 4, ty4 = ty * 4;

    float acc[4][4] = {};

    for (int k0 = 0; k0 < K; k0 += 16) {
#pragma unroll
        for (int i = 0; i < 4; i++) {
            int e = tid + i * 256;
            int k = e & 15, m = e >> 4;
            As[m][k] = A[(long long)(m0 + m) * lda + (k0 + k)];
        }
#pragma unroll
        for (int i = 0; i < 4; i++) {
            int e = tid + i * 256;
            int n = e & 63, k = e >> 6;
            Ws[k][n] = B[(long long)(k0 + k) * ldb + (n0 + n)];
        }
        __syncthreads();
#pragma unroll
        for (int k = 0; k < 16; k++) {
            float4 bv = *(const float4*)(&Ws[k][tx4]);
            float bb[4] = {bv.x, bv.y, bv.z, bv.w};
            float aa[4];
#pragma unroll
            for (int i = 0; i < 4; i++) aa[i] = As[ty4 + i][k];
#pragma unroll
            for (int i = 0; i < 4; i++)
#pragma unroll
                for (int j = 0; j < 4; j++)
                    acc[i][j] = fmaf(aa[i], bb[j], acc[i][j]);
        }
        __syncthreads();
    }

#pragma unroll
    for (int i = 0; i < 4; i++) {
        int m = m0 + ty4 + i;
#pragma unroll
        for (int j = 0; j < 4; j++) {
            int n = n0 + tx4 + j;
            float v = acc[i][j];
            if (bias) v += bias[n];
            if (act == 1) v = gelu_new(v);
            if (res) v += res[(long long)m * ldres + n];
            C[(long long)m * ldc + n] = v;
        }
    }
}

// ---------------------------------------------------------------------------
// Attention scores: S[h,q,k] = (Q[q,:] . K[k,:]) / 8, fused mask (+bias).
// mode 0: causal (k<=q).  mode 1: tril diag=2 (k<=q+2) + scorer bias[k].
// One block computes a 64x64 score tile for head z. K-dim = HD = 64.
// ---------------------------------------------------------------------------
__global__ void scores_kernel(const float* __restrict__ Q, int ldq,
                              const float* __restrict__ Kmat, int ldk,
                              const float* __restrict__ kbias,
                              float* __restrict__ Sout, int mode)
{
    __shared__ float Qs[64][65];  // [q][d] padded
    __shared__ float Ks[64][65];  // [k][d] padded

    int h = blockIdx.z;
    const float* Qg = Q + h * HEADD;
    const float* Kg = Kmat + h * HEADD;
    int q0 = blockIdx.y * 64;
    int k0 = blockIdx.x * 64;
    int tid = threadIdx.x;
    int tx = tid & 15, ty = tid >> 4;
    int tx4 = tx * 4, ty4 = ty * 4;

#pragma unroll
    for (int i = 0; i < 16; i++) {
        int e = tid + i * 256;
        int d = e & 63, r = e >> 6;
        Qs[r][d] = Qg[(long long)(q0 + r) * ldq + d];
        Ks[r][d] = Kg[(long long)(k0 + r) * ldk + d];
    }
    __syncthreads();

    float acc[4][4] = {};
#pragma unroll 8
    for (int d = 0; d < 64; d++) {
        float aa[4], bb[4];
#pragma unroll
        for (int i = 0; i < 4; i++) aa[i] = Qs[ty4 + i][d];
#pragma unroll
        for (int j = 0; j < 4; j++) bb[j] = Ks[tx4 + j][d];
#pragma unroll
        for (int i = 0; i < 4; i++)
#pragma unroll
            for (int j = 0; j < 4; j++)
                acc[i][j] = fmaf(aa[i], bb[j], acc[i][j]);
    }

#pragma unroll
    for (int i = 0; i < 4; i++) {
        int q = q0 + ty4 + i;
#pragma unroll
        for (int j = 0; j < 4; j++) {
            int k = k0 + tx4 + j;
            float v = acc[i][j] * 0.125f;  // 1/sqrt(64)
            bool ok;
            if (mode == 0) {
                ok = (k <= q);
            } else {
                ok = (k <= q + 2);
                v += kbias[k];
            }
            v = ok ? v : -1e30f;
            Sout[((long long)h * S_LEN + q) * S_LEN + k] = v;
        }
    }
}

// ---------------------------------------------------------------------------
// Row softmax over 2048 cols; one block per row, 256 threads, 8 elems/thread.
// ---------------------------------------------------------------------------
__global__ void softmax_kernel(float* __restrict__ Sm)
{
    float* row = Sm + (long long)blockIdx.x * S_LEN;
    int tid = threadIdx.x;

    float vals[8];
    float mx = -3.4e38f;
#pragma unroll
    for (int i = 0; i < 8; i++) {
        vals[i] = row[tid + i * 256];
        mx = fmaxf(mx, vals[i]);
    }
    __shared__ float red[256];
    red[tid] = mx;
    __syncthreads();
#pragma unroll
    for (int st = 128; st >= 1; st >>= 1) {
        if (tid < st) red[tid] = fmaxf(red[tid], red[tid + st]);
        __syncthreads();
    }
    mx = red[0];
    __syncthreads();

    float sum = 0.f;
#pragma unroll
    for (int i = 0; i < 8; i++) {
        vals[i] = __expf(vals[i] - mx);
        sum += vals[i];
    }
    red[tid] = sum;
    __syncthreads();
#pragma unroll
    for (int st = 128; st >= 1; st >>= 1) {
        if (tid < st) red[tid] += red[tid + st];
        __syncthreads();
    }
    float inv = 1.0f / red[0];
#pragma unroll
    for (int i = 0; i < 8; i++)
        row[tid + i * 256] = vals[i] * inv;
}

// ---------------------------------------------------------------------------
extern "C" void kernel_launch(void* const* d_in, const int* in_sizes, int n_in,
                              void* d_out, int out_size)
{
    const float* hidden      = (const float*)d_in[0];
    const float* enc         = (const float*)d_in[1];
    const float* scorer      = (const float*)d_in[2];
    const float* ln1_g       = (const float*)d_in[3];
    const float* ln1_b       = (const float*)d_in[4];
    const float* c_attn_w    = (const float*)d_in[5];
    const float* c_attn_b    = (const float*)d_in[6];
    const float* attn_proj_w = (const float*)d_in[7];
    const float* attn_proj_b = (const float*)d_in[8];
    const float* lnx_g       = (const float*)d_in[9];
    const float* lnx_b       = (const float*)d_in[10];
    const float* q_attn_w    = (const float*)d_in[11];
    const float* q_attn_b    = (const float*)d_in[12];
    const float* x_kv_w      = (const float*)d_in[13];
    const float* x_kv_b      = (const float*)d_in[14];
    const float* x_proj_w    = (const float*)d_in[15];
    const float* x_proj_b    = (const float*)d_in[16];
    const float* ln2_g       = (const float*)d_in[17];
    const float* ln2_b       = (const float*)d_in[18];
    const float* fc_w        = (const float*)d_in[19];
    const float* fc_b        = (const float*)d_in[20];
    const float* mlp_proj_w  = (const float*)d_in[21];
    const float* mlp_proj_b  = (const float*)d_in[22];
    float* out = (float*)d_out;

    float *x, *qkv, *scores, *attn, *hid2, *hid3, *qb, *kv, *mlp;
    cudaGetSymbolAddress((void**)&x, g_x);
    cudaGetSymbolAddress((void**)&qkv, g_qkv);
    cudaGetSymbolAddress((void**)&scores, g_scores);
    cudaGetSymbolAddress((void**)&attn, g_attn);
    cudaGetSymbolAddress((void**)&hid2, g_hid2);
    cudaGetSymbolAddress((void**)&hid3, g_hid3);
    cudaGetSymbolAddress((void**)&qb, g_q);
    cudaGetSymbolAddress((void**)&kv, g_kv);
    cudaGetSymbolAddress((void**)&mlp, g_mlp);

    const long long SS = (long long)S_LEN * S_LEN;

    // ---- self attention ----
    ln_kernel<<<S_LEN, 256>>>(hidden, ln1_g, ln1_b, x);
    // qkv = x @ c_attn_w + b      [2048,1024]@[1024,3072]
    gemm_kernel<<<dim3(48, 32, 1), 256>>>(x, H_DIM, 0, c_attn_w, 3 * H_DIM, 0,
                                          c_attn_b, nullptr, 0,
                                          qkv, 3 * H_DIM, 0, H_DIM, 0);
    // scores (causal)
    scores_kernel<<<dim3(32, 32, NHEAD), 256>>>(qkv, 3 * H_DIM,
                                                qkv + H_DIM, 3 * H_DIM,
                                                nullptr, scores, 0);
    softmax_kernel<<<NHEAD * S_LEN, 256>>>(scores);
    // attn = P @ V (batched over heads), written into merged [q, h*64+d] layout
    gemm_kernel<<<dim3(1, 32, NHEAD), 256>>>(scores, S_LEN, SS,
                                             qkv + 2 * H_DIM, 3 * H_DIM, HEADD,
                                             nullptr, nullptr, 0,
                                             attn, H_DIM, HEADD, S_LEN, 0);
    // hid2 = attn @ attn_proj_w + b + hidden
    gemm_kernel<<<dim3(16, 32, 1), 256>>>(attn, H_DIM, 0, attn_proj_w, H_DIM, 0,
                                          attn_proj_b, hidden, H_DIM,
                                          hid2, H_DIM, 0, H_DIM, 0);

    // ---- cross attention ----
    ln_kernel<<<S_LEN, 256>>>(hid2, lnx_g, lnx_b, x);
    gemm_kernel<<<dim3(16, 32, 1), 256>>>(x, H_DIM, 0, q_attn_w, H_DIM, 0,
                                          q_attn_b, nullptr, 0,
                                          qb, H_DIM, 0, H_DIM, 0);
    // kv = enc @ x_kv_w + b    [2048,1024]@[1024,2048]
    gemm_kernel<<<dim3(32, 32, 1), 256>>>(enc, H_DIM, 0, x_kv_w, 2 * H_DIM, 0,
                                          x_kv_b, nullptr, 0,
                                          kv, 2 * H_DIM, 0, H_DIM, 0);
    // scores (tril diag=2, scorer bias)
    scores_kernel<<<dim3(32, 32, NHEAD), 256>>>(qb, H_DIM, kv, 2 * H_DIM,
                                                scorer, scores, 1);
    softmax_kernel<<<NHEAD * S_LEN, 256>>>(scores);
    gemm_kernel<<<dim3(1, 32, NHEAD), 256>>>(scores, S_LEN, SS,
                                             kv + H_DIM, 2 * H_DIM, HEADD,
                                             nullptr, nullptr, 0,
                                             attn, H_DIM, HEADD, S_LEN, 0);
    // hid3 = attn @ x_proj_w + b + hid2
    gemm_kernel<<<dim3(16, 32, 1), 256>>>(attn, H_DIM, 0, x_proj_w, H_DIM, 0,
                                          x_proj_b, hid2, H_DIM,
                                          hid3, H_DIM, 0, H_DIM, 0);

    // ---- MLP ----
    ln_kernel<<<S_LEN, 256>>>(hid3, ln2_g, ln2_b, x);
    // mlp = gelu(x @ fc_w + b)   [2048,1024]@[1024,4096]
    gemm_kernel<<<dim3(64, 32, 1), 256>>>(x, H_DIM, 0, fc_w, INNER_DIM, 0,
                                          fc_b, nullptr, 0,
                                          mlp, INNER_DIM, 0, H_DIM, 1);
    // out = mlp @ mlp_proj_w + b + hid3
    gemm_kernel<<<dim3(16, 32, 1), 256>>>(mlp, INNER_DIM, 0, mlp_proj_w, H_DIM, 0,
                                          mlp_proj_b, hid3, H_DIM,
                                          out, H_DIM, 0, INNER_DIM, 0);
}

// round 2
// speedup vs baseline: 1.0007x; 1.0007x over previous
#include <cuda_runtime.h>
#include <math.h>

#define S_LEN 2048
#define H_DIM 1024
#define NHEAD 16
#define HEADD 64
#define INNER_DIM 4096

// ---- scratch (static __device__ allowed; no cudaMalloc anywhere) ----
__device__ float g_x[S_LEN * H_DIM];                       // LN output, reused 3x
__device__ float g_qkv[S_LEN * 3 * H_DIM];                 // self-attn qkv
__device__ float g_scores[(size_t)NHEAD * S_LEN * S_LEN];  // 256MB score scratch, reused
__device__ float g_attn[S_LEN * H_DIM];                    // merged attention output
__device__ float g_hid2[S_LEN * H_DIM];                    // after self-attn residual
__device__ float g_hid3[S_LEN * H_DIM];                    // after cross-attn residual
__device__ float g_q[S_LEN * H_DIM];                       // cross-attn q
__device__ float g_kv[S_LEN * 2 * H_DIM];                  // cross-attn kv
__device__ float g_mlp[S_LEN * INNER_DIM];                 // MLP inner

__device__ __forceinline__ float gelu_new(float x) {
    const float c = 0.7978845608028654f;  // sqrt(2/pi)
    float t = tanhf(c * (x + 0.044715f * x * x * x));
    return 0.5f * x * (1.0f + t);
}

// ---------------------------------------------------------------------------
// LayerNorm: one block per row of H=1024, 256 threads, 4 elems/thread.
// ---------------------------------------------------------------------------
__global__ void ln_kernel(const float* __restrict__ X, const float* __restrict__ g,
                          const float* __restrict__ b, float* __restrict__ Y)
{
    const float* x = X + (long long)blockIdx.x * H_DIM;
    float* y = Y + (long long)blockIdx.x * H_DIM;
    int tid = threadIdx.x;

    float v[4];
    float s = 0.f, ss = 0.f;
#pragma unroll
    for (int i = 0; i < 4; i++) {
        v[i] = x[tid + i * 256];
        s += v[i];
        ss += v[i] * v[i];
    }
    __shared__ float r1[256], r2[256];
    r1[tid] = s; r2[tid] = ss;
    __syncthreads();
#pragma unroll
    for (int st = 128; st >= 1; st >>= 1) {
        if (tid < st) { r1[tid] += r1[tid + st]; r2[tid] += r2[tid + st]; }
        __syncthreads();
    }
    float mean = r1[0] * (1.0f / H_DIM);
    float var = r2[0] * (1.0f / H_DIM) - mean * mean;
    float inv = rsqrtf(var + 1e-5f);
#pragma unroll
    for (int i = 0; i < 4; i++) {
        int c = tid + i * 256;
        y[c] = (v[i] - mean) * inv * g[c] + b[c];
    }
}

// ---------------------------------------------------------------------------
// Generic tiled GEMM: C[M,N] = A[M,K] @ B[K,N] (+bias, +gelu, +residual).
// 64x64 tile, BK=16, 256 threads, 4x4 per thread. Batched via z strides.
// All dims are exact multiples of tile sizes for this problem -> no guards.
// ---------------------------------------------------------------------------
__global__ void gemm_kernel(const float* __restrict__ A, int lda, long long aBatch,
                            const float* __restrict__ B, int ldb, long long bBatch,
                            const float* __restrict__ bias,
                            const float* __restrict__ res, int ldres,
                            float* __restrict__ C, int ldc, long long cBatch,
                            int K, int act)
{
    __shared__ float As[64][17];   // [m][k], padded: conflict-free store + broadcast read
    __shared__ float Ws[16][64];   // [k][n], float4 reads

    long long z = blockIdx.z;
    A += z * aBatch; B += z * bBatch; C += z * cBatch;

    int m0 = blockIdx.y * 64;
    int n0 = blockIdx.x * 64;
    int tid = threadIdx.x;
    int tx = tid & 15, ty = tid >> 4;
    int tx4 = tx * 4, ty4 = ty * 4;

    float acc[4][4] = {};

    for (int k0 = 0; k0 < K; k0 += 16) {
#pragma unroll
        for (int i = 0; i < 4; i++) {
            int e = tid + i * 256;
            int k = e & 15, m = e >> 4;
            As[m][k] = A[(long long)(m0 + m) * lda + (k0 + k)];
        }
#pragma unroll
        for (int i = 0; i < 4; i++) {
            int e = tid + i * 256;
            int n = e & 63, k = e >> 6;
            Ws[k][n] = B[(long long)(k0 + k) * ldb + (n0 + n)];
        }
        __syncthreads();
#pragma unroll
        for (int k = 0; k < 16; k++) {
            float4 bv = *(const float4*)(&Ws[k][tx4]);
            float bb[4] = {bv.x, bv.y, bv.z, bv.w};
            float aa[4];
#pragma unroll
            for (int i = 0; i < 4; i++) aa[i] = As[ty4 + i][k];
#pragma unroll
            for (int i = 0; i < 4; i++)
#pragma unroll
                for (int j = 0; j < 4; j++)
                    acc[i][j] = fmaf(aa[i], bb[j], acc[i][j]);
        }
        __syncthreads();
    }

#pragma unroll
    for (int i = 0; i < 4; i++) {
        int m = m0 + ty4 + i;
#pragma unroll
        for (int j = 0; j < 4; j++) {
            int n = n0 + tx4 + j;
            float v = acc[i][j];
            if (bias) v += bias[n];
            if (act == 1) v = gelu_new(v);
            if (res) v += res[(long long)m * ldres + n];
            C[(long long)m * ldc + n] = v;
        }
    }
}

// ---------------------------------------------------------------------------
// Attention scores: S[h,q,k] = (Q[q,:] . K[k,:]) / 8, fused mask (+bias).
// mode 0: causal (k<=q).  mode 1: tril diag=2 (k<=q+2) + scorer bias[k].
// One block computes a 64x64 score tile for head z. K-dim = HD = 64.
// ---------------------------------------------------------------------------
__global__ void scores_kernel(const float* __restrict__ Q, int ldq,
                              const float* __restrict__ Kmat, int ldk,
                              const float* __restrict__ kbias,
                              float* __restrict__ Sout, int mode)
{
    __shared__ float Qs[64][65];  // [q][d] padded
    __shared__ float Ks[64][65];  // [k][d] padded

    int h = blockIdx.z;
    const float* Qg = Q + h * HEADD;
    const float* Kg = Kmat + h * HEADD;
    int q0 = blockIdx.y * 64;
    int k0 = blockIdx.x * 64;
    int tid = threadIdx.x;
    int tx = tid & 15, ty = tid >> 4;
    int tx4 = tx * 4, ty4 = ty * 4;

#pragma unroll
    for (int i = 0; i < 16; i++) {
        int e = tid + i * 256;
        int d = e & 63, r = e >> 6;
        Qs[r][d] = Qg[(long long)(q0 + r) * ldq + d];
        Ks[r][d] = Kg[(long long)(k0 + r) * ldk + d];
    }
    __syncthreads();

    float acc[4][4] = {};
#pragma unroll 8
    for (int d = 0; d < 64; d++) {
        float aa[4], bb[4];
#pragma unroll
        for (int i = 0; i < 4; i++) aa[i] = Qs[ty4 + i][d];
#pragma unroll
        for (int j = 0; j < 4; j++) bb[j] = Ks[tx4 + j][d];
#pragma unroll
        for (int i = 0; i < 4; i++)
#pragma unroll
            for (int j = 0; j < 4; j++)
                acc[i][j] = fmaf(aa[i], bb[j], acc[i][j]);
    }

#pragma unroll
    for (int i = 0; i < 4; i++) {
        int q = q0 + ty4 + i;
#pragma unroll
        for (int j = 0; j < 4; j++) {
            int k = k0 + tx4 + j;
            float v = acc[i][j] * 0.125f;  // 1/sqrt(64)
            bool ok;
            if (mode == 0) {
                ok = (k <= q);
            } else {
                ok = (k <= q + 2);
                v += kbias[k];
            }
            v = ok ? v : -1e30f;
            Sout[((long long)h * S_LEN + q) * S_LEN + k] = v;
        }
    }
}

// ---------------------------------------------------------------------------
// Row softmax over 2048 cols; one block per row, 256 threads, 8 elems/thread.
// ---------------------------------------------------------------------------
__global__ void softmax_kernel(float* __restrict__ Sm)
{
    float* row = Sm + (long long)blockIdx.x * S_LEN;
    int tid = threadIdx.x;

    float vals[8];
    float mx = -3.4e38f;
#pragma unroll
    for (int i = 0; i < 8; i++) {
        vals[i] = row[tid + i * 256];
        mx = fmaxf(mx, vals[i]);
    }
    __shared__ float red[256];
    red[tid] = mx;
    __syncthreads();
#pragma unroll
    for (int st = 128; st >= 1; st >>= 1) {
        if (tid < st) red[tid] = fmaxf(red[tid], red[tid + st]);
        __syncthreads();
    }
    mx = red[0];
    __syncthreads();

    float sum = 0.f;
#pragma unroll
    for (int i = 0; i < 8; i++) {
        vals[i] = __expf(vals[i] - mx);
        sum += vals[i];
    }
    red[tid] = sum;
    __syncthreads();
#pragma unroll
    for (int st = 128; st >= 1; st >>= 1) {
        if (tid < st) red[tid] += red[tid + st];
        __syncthreads();
    }
    float inv = 1.0f / red[0];
#pragma unroll
    for (int i = 0; i < 8; i++)
        row[tid + i * 256] = vals[i] * inv;
}

// ---------------------------------------------------------------------------
extern "C" void kernel_launch(void* const* d_in, const int* in_sizes, int n_in,
                              void* d_out, int out_size)
{
    const float* hidden      = (const float*)d_in[0];
    const float* enc         = (const float*)d_in[1];
    const float* scorer      = (const float*)d_in[2];
    const float* ln1_g       = (const float*)d_in[3];
    const float* ln1_b       = (const float*)d_in[4];
    const float* c_attn_w    = (const float*)d_in[5];
    const float* c_attn_b    = (const float*)d_in[6];
    const float* attn_proj_w = (const float*)d_in[7];
    const float* attn_proj_b = (const float*)d_in[8];
    const float* lnx_g       = (const float*)d_in[9];
    const float* lnx_b       = (const float*)d_in[10];
    const float* q_attn_w    = (const float*)d_in[11];
    const float* q_attn_b    = (const float*)d_in[12];
    const float* x_kv_w      = (const float*)d_in[13];
    const float* x_kv_b      = (const float*)d_in[14];
    const float* x_proj_w    = (const float*)d_in[15];
    const float* x_proj_b    = (const float*)d_in[16];
    const float* ln2_g       = (const float*)d_in[17];
    const float* ln2_b       = (const float*)d_in[18];
    const float* fc_w        = (const float*)d_in[19];
    const float* fc_b        = (const float*)d_in[20];
    const float* mlp_proj_w  = (const float*)d_in[21];
    const float* mlp_proj_b  = (const float*)d_in[22];
    float* out = (float*)d_out;

    float *x, *qkv, *scores, *attn, *hid2, *hid3, *qb, *kv, *mlp;
    cudaGetSymbolAddress((void**)&x, g_x);
    cudaGetSymbolAddress((void**)&qkv, g_qkv);
    cudaGetSymbolAddress((void**)&scores, g_scores);
    cudaGetSymbolAddress((void**)&attn, g_attn);
    cudaGetSymbolAddress((void**)&hid2, g_hid2);
    cudaGetSymbolAddress((void**)&hid3, g_hid3);
    cudaGetSymbolAddress((void**)&qb, g_q);
    cudaGetSymbolAddress((void**)&kv, g_kv);
    cudaGetSymbolAddress((void**)&mlp, g_mlp);

    const long long SS = (long long)S_LEN * S_LEN;

    // ---- self attention ----
    ln_kernel<<<S_LEN, 256>>>(hidden, ln1_g, ln1_b, x);
    // qkv = x @ c_attn_w + b      [2048,1024]@[1024,3072]
    gemm_kernel<<<dim3(48, 32, 1), 256>>>(x, H_DIM, 0, c_attn_w, 3 * H_DIM, 0,
                                          c_attn_b, nullptr, 0,
                                          qkv, 3 * H_DIM, 0, H_DIM, 0);
    // scores (causal)
    scores_kernel<<<dim3(32, 32, NHEAD), 256>>>(qkv, 3 * H_DIM,
                                                qkv + H_DIM, 3 * H_DIM,
                                                nullptr, scores, 0);
    softmax_kernel<<<NHEAD * S_LEN, 256>>>(scores);
    // attn = P @ V (batched over heads), written into merged [q, h*64+d] layout
    gemm_kernel<<<dim3(1, 32, NHEAD), 256>>>(scores, S_LEN, SS,
                                             qkv + 2 * H_DIM, 3 * H_DIM, HEADD,
                                             nullptr, nullptr, 0,
                                             attn, H_DIM, HEADD, S_LEN, 0);
    // hid2 = attn @ attn_proj_w + b + hidden
    gemm_kernel<<<dim3(16, 32, 1), 256>>>(attn, H_DIM, 0, attn_proj_w, H_DIM, 0,
                                          attn_proj_b, hidden, H_DIM,
                                          hid2, H_DIM, 0, H_DIM, 0);

    // ---- cross attention ----
    ln_kernel<<<S_LEN, 256>>>(hid2, lnx_g, lnx_b, x);
    gemm_kernel<<<dim3(16, 32, 1), 256>>>(x, H_DIM, 0, q_attn_w, H_DIM, 0,
                                          q_attn_b, nullptr, 0,
                                          qb, H_DIM, 0, H_DIM, 0);
    // kv = enc @ x_kv_w + b    [2048,1024]@[1024,2048]
    gemm_kernel<<<dim3(32, 32, 1), 256>>>(enc, H_DIM, 0, x_kv_w, 2 * H_DIM, 0,
                                          x_kv_b, nullptr, 0,
                                          kv, 2 * H_DIM, 0, H_DIM, 0);
    // scores (tril diag=2, scorer bias)
    scores_kernel<<<dim3(32, 32, NHEAD), 256>>>(qb, H_DIM, kv, 2 * H_DIM,
                                                scorer, scores, 1);
    softmax_kernel<<<NHEAD * S_LEN, 256>>>(scores);
    gemm_kernel<<<dim3(1, 32, NHEAD), 256>>>(scores, S_LEN, SS,
                                             kv + H_DIM, 2 * H_DIM, HEADD,
                                             nullptr, nullptr, 0,
                                             attn, H_DIM, HEADD, S_LEN, 0);
    // hid3 = attn @ x_proj_w + b + hid2
    gemm_kernel<<<dim3(16, 32, 1), 256>>>(attn, H_DIM, 0, x_proj_w, H_DIM, 0,
                                          x_proj_b, hid2, H_DIM,
                                          hid3, H_DIM, 0, H_DIM, 0);

    // ---- MLP ----
    ln_kernel<<<S_LEN, 256>>>(hid3, ln2_g, ln2_b, x);
    // mlp = gelu(x @ fc_w + b)   [2048,1024]@[1024,4096]
    gemm_kernel<<<dim3(64, 32, 1), 256>>>(x, H_DIM, 0, fc_w, INNER_DIM, 0,
                                          fc_b, nullptr, 0,
                                          mlp, INNER_DIM, 0, H_DIM, 1);
    // out = mlp @ mlp_proj_w + b + hid3
    gemm_kernel<<<dim3(16, 32, 1), 256>>>(mlp, INNER_DIM, 0, mlp_proj_w, H_DIM, 0,
                                          mlp_proj_b, hid3, H_DIM,
                                          out, H_DIM, 0, INNER_DIM, 0);
}

// round 8
// speedup vs baseline: 2.2034x; 2.2018x over previous
#include <cuda_runtime.h>
#include <cuda_fp16.h>
#include <stdint.h>
#include <math.h>

#define S_LEN 2048
#define H_DIM 1024
#define NHEAD 16
#define HEADD 64
#define INNER_DIM 4096

// ---------------- scratch ----------------
__device__ float  g_x[S_LEN * H_DIM];
__device__ float  g_qkv[S_LEN * 3 * H_DIM];
__device__ float  g_scores[(size_t)NHEAD * S_LEN * S_LEN];
__device__ __half g_P[(size_t)NHEAD * S_LEN * S_LEN];
__device__ float  g_attn[S_LEN * H_DIM];
__device__ float  g_hid2[S_LEN * H_DIM];
__device__ float  g_hid3[S_LEN * H_DIM];
__device__ float  g_q[S_LEN * H_DIM];
__device__ float  g_kv[S_LEN * 2 * H_DIM];
__device__ float  g_mlp[S_LEN * INNER_DIM];
__device__ float  g_vt[H_DIM * S_LEN];
__device__ float  g_wt[16 * 1024 * 1024];

#define WT_CA  0
#define WT_AP  3145728
#define WT_QA  4194304
#define WT_XKV 5242880
#define WT_XP  7340032
#define WT_FC  8388608
#define WT_MP  12582912

#define SM_STRIDE 40   // halves per smem row (32 data + 8 pad)

__device__ __forceinline__ float gelu_new(float x) {
    const float c = 0.7978845608028654f;
    return 0.5f * x * (1.0f + tanhf(c * (x + 0.044715f * x * x * x)));
}

// ---- HMMA m16n8k16 f16f16f32 ----
__device__ __forceinline__ void mma_16816(float c[4], const uint32_t a[4], const uint32_t b[2]) {
    asm volatile("mma.sync.aligned.m16n8k16.row.col.f32.f16.f16.f32 "
        "{%0,%1,%2,%3}, {%4,%5,%6,%7}, {%8,%9}, {%0,%1,%2,%3};"
        : "+f"(c[0]), "+f"(c[1]), "+f"(c[2]), "+f"(c[3])
        : "r"(a[0]), "r"(a[1]), "r"(a[2]), "r"(a[3]), "r"(b[0]), "r"(b[1]));
}

// A fragment (16x16 row-major) from smem [m][k] stride 40
__device__ __forceinline__ void lda4(uint32_t a[4], const __half* S, int row0, int kk, int lane) {
    const __half* p = S + (row0 + (lane >> 2)) * SM_STRIDE + kk + ((lane & 3) << 1);
    a[0] = *(const uint32_t*)p;
    a[1] = *(const uint32_t*)(p + 8 * SM_STRIDE);
    a[2] = *(const uint32_t*)(p + 8);
    a[3] = *(const uint32_t*)(p + 8 * SM_STRIDE + 8);
}
// B fragment (16x8 col-major) from smem [n][k] stride 40
__device__ __forceinline__ void ldb2(uint32_t b[2], const __half* S, int n0, int kk, int lane) {
    const __half* p = S + (n0 + (lane >> 2)) * SM_STRIDE + kk + ((lane & 3) << 1);
    b[0] = *(const uint32_t*)p;
    b[1] = *(const uint32_t*)(p + 8);
}

// ---- gmem fp32 chunk (R rows x 32 cols) -> regs ----
template<int R>
__device__ __forceinline__ void ldg_f32(float4 (&v)[R / 32], const float* A, int lda,
                                        int row0, int k0, int t) {
    constexpr int TPR = 256 / R;
    constexpr int FPT = R / 8;
    int row = t / TPR, seg = t % TPR;
    const float* p = A + (long long)(row0 + row) * lda + k0 + seg * FPT;
#pragma unroll
    for (int i = 0; i < R / 32; i++) v[i] = *(const float4*)(p + i * 4);
}
// regs -> smem hi/lo fp16
template<int R>
__device__ __forceinline__ void sts_hilo(const float4 (&v)[R / 32], __half* hi, __half* lo, int t) {
    constexpr int TPR = 256 / R;
    constexpr int FPT = R / 8;
    int row = t / TPR, seg = t % TPR;
    __half2* ph = (__half2*)(hi + row * SM_STRIDE + seg * FPT);
    __half2* pl = (__half2*)(lo + row * SM_STRIDE + seg * FPT);
    const float* f = (const float*)v;
#pragma unroll
    for (int i = 0; i < FPT / 2; i++) {
        __half h0 = __float2half_rn(f[2 * i]), h1 = __float2half_rn(f[2 * i + 1]);
        ph[i] = __halves2half2(h0, h1);
        pl[i] = __halves2half2(__float2half_rn(f[2 * i] - __half2float(h0)),
                               __float2half_rn(f[2 * i + 1] - __half2float(h1)));
    }
}
// fp16 A (P matrix): 128 rows x 32 halves
__device__ __forceinline__ void ldg_h(uint4 (&v)[2], const __half* A, int lda,
                                      int row0, int k0, int t) {
    int row = t >> 1, seg = t & 1;
    const __half* p = A + (long long)(row0 + row) * lda + k0 + seg * 16;
    v[0] = *(const uint4*)p;
    v[1] = *(const uint4*)(p + 8);
}
__device__ __forceinline__ void sts_h(const uint4 (&v)[2], __half* S, int t) {
    int row = t >> 1, seg = t & 1;
    *(uint4*)(S + row * SM_STRIDE + seg * 16) = v[0];
    *(uint4*)(S + row * SM_STRIDE + seg * 16 + 8) = v[1];
}

// one 32-wide K chunk of MMA work
template<int MT, bool AHALF, int NB>
__device__ __forceinline__ void compute_chunk(float (&acc)[MT][4][4],
    const __half* AsH, const __half* AsL, const __half* BsH, const __half* BsL,
    int wm0, int wn0, int lane)
{
#pragma unroll
    for (int kk = 0; kk < 32; kk += 16) {
        uint32_t a[MT][4], b[4][2];
#pragma unroll
        for (int i = 0; i < MT; i++) lda4(a[i], AsH, wm0 + i * 16, kk, lane);
#pragma unroll
        for (int j = 0; j < 4; j++) ldb2(b[j], BsH, wn0 + j * 8, kk, lane);
#pragma unroll
        for (int i = 0; i < MT; i++)
#pragma unroll
            for (int j = 0; j < 4; j++) mma_16816(acc[i][j], a[i], b[j]);
        if (NB == 2) {
#pragma unroll
            for (int j = 0; j < 4; j++) {
                uint32_t bl[2];
                ldb2(bl, BsL, wn0 + j * 8, kk, lane);
#pragma unroll
                for (int i = 0; i < MT; i++) mma_16816(acc[i][j], a[i], bl);
            }
        }
        if (!AHALF) {
#pragma unroll
            for (int i = 0; i < MT; i++) {
                uint32_t al[4];
                lda4(al, AsL, wm0 + i * 16, kk, lane);
#pragma unroll
                for (int j = 0; j < 4; j++) mma_16816(acc[i][j], al, b[j]);
            }
        }
    }
}

// ---------------------------------------------------------------------------
// HMMA GEMM: C[M,N] = A[M,K] @ B^T (B stored [N,K]). Block 128 x BN, BK=32.
// ---------------------------------------------------------------------------
template<int BN, int MT, bool AHALF, int NB>
__global__ void __launch_bounds__(256) hmma_gemm(
    const void* Av, int lda, long long aB,
    const float* Bm, int ldb, long long bB,
    const float* __restrict__ bias, const float* __restrict__ res, int ldres,
    float* C, int ldc, long long cB, int K, int act)
{
    constexpr int WARPS_M = 128 / (MT * 16);
    constexpr int ASZ = 128 * SM_STRIDE;
    constexpr int BSZ = BN * SM_STRIDE;
    __shared__ __half As[(AHALF ? 1 : 2) * ASZ];
    __shared__ __half Bs[NB * BSZ];

    int t = threadIdx.x, w = t >> 5, lane = t & 31;
    int warpY = w % WARPS_M, warpX = w / WARPS_M;
    int wm0 = warpY * MT * 16, wn0 = warpX * 32;
    int m0 = blockIdx.y * 128, n0 = blockIdx.x * BN;
    long long z = blockIdx.z;
    const float* Af = AHALF ? nullptr : (const float*)Av + z * aB;
    const __half* Ah = AHALF ? (const __half*)Av + z * aB : nullptr;
    const float* Bz = Bm + z * bB;
    float* Cz = C + z * cB;

    float acc[MT][4][4] = {};
    float4 va[4]; uint4 vah[2]; float4 vb[BN / 32];

    if (AHALF) ldg_h(vah, Ah, lda, m0, 0, t);
    else       ldg_f32<128>(va, Af, lda, m0, 0, t);
    ldg_f32<BN>(vb, Bz, ldb, n0, 0, t);

    int nch = K >> 5;
    for (int c = 0; c < nch; c++) {
        if (AHALF) sts_h(vah, As, t);
        else       sts_hilo<128>(va, As, As + ASZ, t);
        sts_hilo<BN>(vb, Bs, Bs + BSZ, t);
        __syncthreads();
        if (c + 1 < nch) {
            int k0 = (c + 1) << 5;
            if (AHALF) ldg_h(vah, Ah, lda, m0, k0, t);
            else       ldg_f32<128>(va, Af, lda, m0, k0, t);
            ldg_f32<BN>(vb, Bz, ldb, n0, k0, t);
        }
        compute_chunk<MT, AHALF, NB>(acc, As, As + ASZ, Bs, Bs + BSZ, wm0, wn0, lane);
        __syncthreads();
    }

    int rb = m0 + wm0 + (lane >> 2);
    int cb = n0 + wn0 + ((lane & 3) << 1);
#pragma unroll
    for (int i = 0; i < MT; i++) {
#pragma unroll
        for (int j = 0; j < 4; j++) {
            int cc = cb + j * 8;
            float b0 = bias ? bias[cc] : 0.f, b1 = bias ? bias[cc + 1] : 0.f;
#pragma unroll
            for (int h = 0; h < 2; h++) {
                int r = rb + i * 16 + h * 8;
                float v0 = acc[i][j][2 * h] + b0;
                float v1 = acc[i][j][2 * h + 1] + b1;
                if (act) { v0 = gelu_new(v0); v1 = gelu_new(v1); }
                if (res) {
                    const float* rp = res + (long long)r * ldres + cc;
                    v0 += rp[0]; v1 += rp[1];
                }
                *(float2*)&Cz[(long long)r * ldc + cc] = make_float2(v0, v1);
            }
        }
    }
}

// ---------------------------------------------------------------------------
// Attention logits: 128q x 128k tile per CTA, inner K = 64 (head dim).
// mode 0: causal mask; mode 1: k<=q+2 mask + scorer bias.
// ---------------------------------------------------------------------------
__global__ void __launch_bounds__(256) hmma_scores(
    const float* Q, int ldq, const float* Km, int ldk,
    const float* __restrict__ kbias, float* __restrict__ Sout, int mode)
{
    constexpr int ASZ = 128 * SM_STRIDE;
    __shared__ __half As[2 * ASZ];
    __shared__ __half Bs[2 * ASZ];

    int t = threadIdx.x, w = t >> 5, lane = t & 31;
    int warpY = w & 1, warpX = w >> 1;
    int wm0 = warpY * 64, wn0 = warpX * 32;
    int h = blockIdx.z, q0 = blockIdx.y * 128, k0 = blockIdx.x * 128;
    const float* Qg = Q + h * HEADD;
    const float* Kg = Km + h * HEADD;

    float acc[4][4][4] = {};
    float4 va[4], vb[4];

    ldg_f32<128>(va, Qg, ldq, q0, 0, t);
    ldg_f32<128>(vb, Kg, ldk, k0, 0, t);
#pragma unroll
    for (int c = 0; c < 2; c++) {
        sts_hilo<128>(va, As, As + ASZ, t);
        sts_hilo<128>(vb, Bs, Bs + ASZ, t);
        __syncthreads();
        if (c == 0) {
            ldg_f32<128>(va, Qg, ldq, q0, 32, t);
            ldg_f32<128>(vb, Kg, ldk, k0, 32, t);
        }
        compute_chunk<4, false, 2>(acc, As, As + ASZ, Bs, Bs + ASZ, wm0, wn0, lane);
        __syncthreads();
    }

    int rb = q0 + wm0 + (lane >> 2);
    int cb = k0 + wn0 + ((lane & 3) << 1);
#pragma unroll
    for (int i = 0; i < 4; i++) {
#pragma unroll
        for (int j = 0; j < 4; j++) {
            int cc = cb + j * 8;
#pragma unroll
            for (int hh = 0; hh < 2; hh++) {
                int q = rb + i * 16 + hh * 8;
                float v0 = acc[i][j][2 * hh] * 0.125f;
                float v1 = acc[i][j][2 * hh + 1] * 0.125f;
                bool ok0, ok1;
                if (mode == 0) { ok0 = (cc <= q); ok1 = (cc + 1 <= q); }
                else {
                    v0 += kbias[cc]; v1 += kbias[cc + 1];
                    ok0 = (cc <= q + 2); ok1 = (cc + 1 <= q + 2);
                }
                float2 o = make_float2(ok0 ? v0 : -1e30f, ok1 ? v1 : -1e30f);
                *(float2*)&Sout[((long long)h * S_LEN + q) * S_LEN + cc] = o;
            }
        }
    }
}

// ---------------------------------------------------------------------------
__global__ void ln_kernel(const float* __restrict__ X, const float* __restrict__ g,
                          const float* __restrict__ b, float* __restrict__ Y)
{
    const float* x = X + (long long)blockIdx.x * H_DIM;
    float* y = Y + (long long)blockIdx.x * H_DIM;
    int tid = threadIdx.x;
    float v[4], s = 0.f, ss = 0.f;
#pragma unroll
    for (int i = 0; i < 4; i++) { v[i] = x[tid + i * 256]; s += v[i]; ss += v[i] * v[i]; }
    __shared__ float r1[256], r2[256];
    r1[tid] = s; r2[tid] = ss;
    __syncthreads();
#pragma unroll
    for (int st = 128; st >= 1; st >>= 1) {
        if (tid < st) { r1[tid] += r1[tid + st]; r2[tid] += r2[tid + st]; }
        __syncthreads();
    }
    float mean = r1[0] * (1.0f / H_DIM);
    float inv = rsqrtf(r2[0] * (1.0f / H_DIM) - mean * mean + 1e-5f);
#pragma unroll
    for (int i = 0; i < 4; i++) {
        int c = tid + i * 256;
        y[c] = (v[i] - mean) * inv * g[c] + b[c];
    }
}

__global__ void softmax_kernel(const float* __restrict__ S, __half* __restrict__ P)
{
    const float* row = S + (long long)blockIdx.x * S_LEN;
    __half* prow = P + (long long)blockIdx.x * S_LEN;
    int tid = threadIdx.x;
    float vals[8], mx = -3.4e38f;
#pragma unroll
    for (int i = 0; i < 8; i++) { vals[i] = row[tid + i * 256]; mx = fmaxf(mx, vals[i]); }
    __shared__ float red[256];
    red[tid] = mx; __syncthreads();
#pragma unroll
    for (int st = 128; st >= 1; st >>= 1) {
        if (tid < st) red[tid] = fmaxf(red[tid], red[tid + st]);
        __syncthreads();
    }
    mx = red[0]; __syncthreads();
    float sum = 0.f;
#pragma unroll
    for (int i = 0; i < 8; i++) { vals[i] = __expf(vals[i] - mx); sum += vals[i]; }
    red[tid] = sum; __syncthreads();
#pragma unroll
    for (int st = 128; st >= 1; st >>= 1) {
        if (tid < st) red[tid] += red[tid + st];
        __syncthreads();
    }
    float inv = 1.0f / red[0];
#pragma unroll
    for (int i = 0; i < 8; i++)
        prow[tid + i * 256] = __float2half_rn(vals[i] * inv);
}

__global__ void transpose_k(const float* __restrict__ in, int ldi,
                            float* __restrict__ out, int ldo)
{
    __shared__ float tbuf[32][33];
    int r0 = blockIdx.y * 32, c0 = blockIdx.x * 32;
    int tx = threadIdx.x, ty = threadIdx.y;
#pragma unroll
    for (int i = 0; i < 4; i++)
        tbuf[ty + i * 8][tx] = in[(long long)(r0 + ty + i * 8) * ldi + c0 + tx];
    __syncthreads();
#pragma unroll
    for (int i = 0; i < 4; i++)
        out[(long long)(c0 + ty + i * 8) * ldo + r0 + tx] = tbuf[tx][ty + i * 8];
}

// ---------------------------------------------------------------------------
extern "C" void kernel_launch(void* const* d_in, const int* in_sizes, int n_in,
                              void* d_out, int out_size)
{
    const float* hidden = (const float*)d_in[0];
    const float* enc    = (const float*)d_in[1];
    const float* scorer = (const float*)d_in[2];
    const float* ln1_g = (const float*)d_in[3],  *ln1_b = (const float*)d_in[4];
    const float* c_attn_w = (const float*)d_in[5], *c_attn_b = (const float*)d_in[6];
    const float* attn_proj_w = (const float*)d_in[7], *attn_proj_b = (const float*)d_in[8];
    const float* lnx_g = (const float*)d_in[9],  *lnx_b = (const float*)d_in[10];
    const float* q_attn_w = (const float*)d_in[11], *q_attn_b = (const float*)d_in[12];
    const float* x_kv_w = (const float*)d_in[13], *x_kv_b = (const float*)d_in[14];
    const float* x_proj_w = (const float*)d_in[15], *x_proj_b = (const float*)d_in[16];
    const float* ln2_g = (const float*)d_in[17], *ln2_b = (const float*)d_in[18];
    const float* fc_w = (const float*)d_in[19], *fc_b = (const float*)d_in[20];
    const float* mlp_proj_w = (const float*)d_in[21], *mlp_proj_b = (const float*)d_in[22];
    float* out = (float*)d_out;

    float *x, *qkv, *scores, *attn, *hid2, *hid3, *qb, *kv, *mlp, *vt, *wt;
    __half* P;
    cudaGetSymbolAddress((void**)&x, g_x);
    cudaGetSymbolAddress((void**)&qkv, g_qkv);
    cudaGetSymbolAddress((void**)&scores, g_scores);
    cudaGetSymbolAddress((void**)&P, g_P);
    cudaGetSymbolAddress((void**)&attn, g_attn);
    cudaGetSymbolAddress((void**)&hid2, g_hid2);
    cudaGetSymbolAddress((void**)&hid3, g_hid3);
    cudaGetSymbolAddress((void**)&qb, g_q);
    cudaGetSymbolAddress((void**)&kv, g_kv);
    cudaGetSymbolAddress((void**)&mlp, g_mlp);
    cudaGetSymbolAddress((void**)&vt, g_vt);
    cudaGetSymbolAddress((void**)&wt, g_wt);

    dim3 tb(32, 8);
    const long long SS = (long long)S_LEN * S_LEN;

    // weight transposes -> [N][K]
    transpose_k<<<dim3(96, 32), tb>>>(c_attn_w, 3072, wt + WT_CA, 1024);
    transpose_k<<<dim3(32, 32), tb>>>(attn_proj_w, 1024, wt + WT_AP, 1024);
    transpose_k<<<dim3(32, 32), tb>>>(q_attn_w, 1024, wt + WT_QA, 1024);
    transpose_k<<<dim3(64, 32), tb>>>(x_kv_w, 2048, wt + WT_XKV, 1024);
    transpose_k<<<dim3(32, 32), tb>>>(x_proj_w, 1024, wt + WT_XP, 1024);
    transpose_k<<<dim3(128, 32), tb>>>(fc_w, 4096, wt + WT_FC, 1024);
    transpose_k<<<dim3(32, 128), tb>>>(mlp_proj_w, 1024, wt + WT_MP, 4096);

    // ---- self attention ----
    ln_kernel<<<S_LEN, 256>>>(hidden, ln1_g, ln1_b, x);
    hmma_gemm<128, 4, false, 2><<<dim3(24, 16, 1), 256>>>(x, 1024, 0, wt + WT_CA, 1024, 0,
        c_attn_b, nullptr, 0, qkv, 3072, 0, 1024, 0);
    transpose_k<<<dim3(32, 64), tb>>>(qkv + 2048, 3072, vt, 2048);   // V^T
    hmma_scores<<<dim3(16, 16, NHEAD), 256>>>(qkv, 3072, qkv + 1024, 3072,
        nullptr, scores, 0);
    softmax_kernel<<<NHEAD * S_LEN, 256>>>(scores, P);
    hmma_gemm<64, 2, true, 2><<<dim3(1, 16, NHEAD), 256>>>(P, 2048, SS, vt, 2048,
        (long long)64 * 2048, nullptr, nullptr, 0, attn, 1024, 64, 2048, 0);
    hmma_gemm<128, 4, false, 2><<<dim3(8, 16, 1), 256>>>(attn, 1024, 0, wt + WT_AP, 1024, 0,
        attn_proj_b, hidden, 1024, hid2, 1024, 0, 1024, 0);

    // ---- cross attention ----
    ln_kernel<<<S_LEN, 256>>>(hid2, lnx_g, lnx_b, x);
    hmma_gemm<128, 4, false, 2><<<dim3(8, 16, 1), 256>>>(x, 1024, 0, wt + WT_QA, 1024, 0,
        q_attn_b, nullptr, 0, qb, 1024, 0, 1024, 0);
    hmma_gemm<128, 4, false, 2><<<dim3(16, 16, 1), 256>>>(enc, 1024, 0, wt + WT_XKV, 1024, 0,
        x_kv_b, nullptr, 0, kv, 2048, 0, 1024, 0);
    transpose_k<<<dim3(32, 64), tb>>>(kv + 1024, 2048, vt, 2048);    // V^T
    hmma_scores<<<dim3(16, 16, NHEAD), 256>>>(qb, 1024, kv, 2048,
        scorer, scores, 1);
    softmax_kernel<<<NHEAD * S_LEN, 256>>>(scores, P);
    hmma_gemm<64, 2, true, 2><<<dim3(1, 16, NHEAD), 256>>>(P, 2048, SS, vt, 2048,
        (long long)64 * 2048, nullptr, nullptr, 0, attn, 1024, 64, 2048, 0);
    hmma_gemm<128, 4, false, 2><<<dim3(8, 16, 1), 256>>>(attn, 1024, 0, wt + WT_XP, 1024, 0,
        x_proj_b, hid2, 1024, hid3, 1024, 0, 1024, 0);

    // ---- MLP ----
    ln_kernel<<<S_LEN, 256>>>(hid3, ln2_g, ln2_b, x);
    hmma_gemm<128, 4, false, 2><<<dim3(32, 16, 1), 256>>>(x, 1024, 0, wt + WT_FC, 1024, 0,
        fc_b, nullptr, 0, mlp, 4096, 0, 1024, 1);
    hmma_gemm<128, 4, false, 2><<<dim3(8, 16, 1), 256>>>(mlp, 4096, 0, wt + WT_MP, 4096, 0,
        mlp_proj_b, hid3, 1024, out, 1024, 0, 4096, 0);
}

// round 10
// speedup vs baseline: 2.6035x; 1.1816x over previous
#include <cuda_runtime.h>
#include <cuda_fp16.h>
#include <stdint.h>
#include <math.h>

#define S_LEN 2048
#define H_DIM 1024
#define NHEAD 16
#define HEADD 64
#define INNER_DIM 4096

// ---------------- scratch ----------------
__device__ float  g_x[S_LEN * H_DIM];
__device__ float  g_qkv[S_LEN * 3 * H_DIM];
__device__ float  g_scores[(size_t)NHEAD * S_LEN * S_LEN];
__device__ __half g_P[(size_t)NHEAD * S_LEN * S_LEN];
__device__ float  g_attn[S_LEN * H_DIM];
__device__ float  g_hid2[S_LEN * H_DIM];
__device__ float  g_hid3[S_LEN * H_DIM];
__device__ float  g_q[S_LEN * H_DIM];
__device__ float  g_kv[S_LEN * 2 * H_DIM];
__device__ float  g_mlp[S_LEN * INNER_DIM];
__device__ __half g_wh[33554432];          // weights: hi plane then lo plane per weight
__device__ __half g_vth[4194304];          // V^T: hi plane (2M) + lo plane (2M)

// half-plane offsets (in halves); each weight occupies 2*size
#define WH_CA  0
#define WH_AP  6291456
#define WH_QA  8388608
#define WH_XKV 10485760
#define WH_XP  14680064
#define WH_FC  16777216
#define WH_MP  25165824
#define SZ_CA  3145728
#define SZ_AP  1048576
#define SZ_QA  1048576
#define SZ_XKV 2097152
#define SZ_XP  1048576
#define SZ_FC  4194304
#define SZ_MP  4194304
#define VT_PLANE 2097152

#define SM_STRIDE 40   // halves per smem row (32 data + 8 pad) -> conflict-free ldmatrix

__device__ __forceinline__ float gelu_new(float x) {
    const float c = 0.7978845608028654f;
    return 0.5f * x * (1.0f + tanhf(c * (x + 0.044715f * x * x * x)));
}

__device__ __forceinline__ uint32_t smem_u32(const void* p) {
    uint32_t a;
    asm("{ .reg .u64 t; cvta.to.shared.u64 t, %1; cvt.u32.u64 %0, t; }" : "=r"(a) : "l"(p));
    return a;
}

// ---- HMMA m16n8k16 f16f16f32 ----
__device__ __forceinline__ void mma_16816(float c[4], const uint32_t a[4], const uint32_t b[2]) {
    asm volatile("mma.sync.aligned.m16n8k16.row.col.f32.f16.f16.f32 "
        "{%0,%1,%2,%3}, {%4,%5,%6,%7}, {%8,%9}, {%0,%1,%2,%3};"
        : "+f"(c[0]), "+f"(c[1]), "+f"(c[2]), "+f"(c[3])
        : "r"(a[0]), "r"(a[1]), "r"(a[2]), "r"(a[3]), "r"(b[0]), "r"(b[1]));
}
__device__ __forceinline__ void ldm_x4(uint32_t r[4], uint32_t addr) {
    asm volatile("ldmatrix.sync.aligned.m8n8.x4.shared.b16 {%0,%1,%2,%3}, [%4];"
        : "=r"(r[0]), "=r"(r[1]), "=r"(r[2]), "=r"(r[3]) : "r"(addr));
}

// ---- gmem fp32 chunk (R rows x 32 cols) -> regs ----
template<int R>
__device__ __forceinline__ void ldg_f32(float4 (&v)[R / 32], const float* A, int lda,
                                        int row0, int k0, int t) {
    constexpr int TPR = 256 / R;
    constexpr int FPT = R / 8;
    int row = t / TPR, seg = t % TPR;
    const float* p = A + (long long)(row0 + row) * lda + k0 + seg * FPT;
#pragma unroll
    for (int i = 0; i < R / 32; i++) v[i] = *(const float4*)(p + i * 4);
}
template<int R>
__device__ __forceinline__ void sts_hilo(const float4 (&v)[R / 32], __half* hi, __half* lo, int t) {
    constexpr int TPR = 256 / R;
    constexpr int FPT = R / 8;
    int row = t / TPR, seg = t % TPR;
    __half2* ph = (__half2*)(hi + row * SM_STRIDE + seg * FPT);
    __half2* pl = (__half2*)(lo + row * SM_STRIDE + seg * FPT);
    const float* f = (const float*)v;
#pragma unroll
    for (int i = 0; i < FPT / 2; i++) {
        __half h0 = __float2half_rn(f[2 * i]), h1 = __float2half_rn(f[2 * i + 1]);
        ph[i] = __halves2half2(h0, h1);
        pl[i] = __halves2half2(__float2half_rn(f[2 * i] - __half2float(h0)),
                               __float2half_rn(f[2 * i + 1] - __half2float(h1)));
    }
}
// fp16 dual-plane B chunk (R rows x 32 halves per plane)
template<int R>
__device__ __forceinline__ void ldg_h2(uint4 (&vh)[R / 64], uint4 (&vl)[R / 64],
                                       const __half* Bh, const __half* Bl,
                                       int ldb, int n0, int k0, int t) {
    constexpr int TPR = 256 / R;
    constexpr int HPT = 32 / TPR;
    int row = t / TPR, seg = t % TPR;
    const __half* ph = Bh + (long long)(n0 + row) * ldb + k0 + seg * HPT;
    const __half* pl = Bl + (long long)(n0 + row) * ldb + k0 + seg * HPT;
#pragma unroll
    for (int u = 0; u < R / 64; u++) { vh[u] = ((const uint4*)ph)[u]; vl[u] = ((const uint4*)pl)[u]; }
}
template<int R>
__device__ __forceinline__ void sts_h2(const uint4 (&vh)[R / 64], const uint4 (&vl)[R / 64],
                                       __half* hi, __half* lo, int t) {
    constexpr int TPR = 256 / R;
    constexpr int HPT = 32 / TPR;
    int row = t / TPR, seg = t % TPR;
    __half* ph = hi + row * SM_STRIDE + seg * HPT;
    __half* pl = lo + row * SM_STRIDE + seg * HPT;
#pragma unroll
    for (int u = 0; u < R / 64; u++) { ((uint4*)ph)[u] = vh[u]; ((uint4*)pl)[u] = vl[u]; }
}
// fp16 single-plane A (P matrix): 128 rows x 32 halves
__device__ __forceinline__ void ldg_h(uint4 (&v)[2], const __half* A, int lda,
                                      int row0, int k0, int t) {
    int row = t >> 1, seg = t & 1;
    const __half* p = A + (long long)(row0 + row) * lda + k0 + seg * 16;
    v[0] = *(const uint4*)p;
    v[1] = *(const uint4*)(p + 8);
}
__device__ __forceinline__ void sts_h(const uint4 (&v)[2], __half* S, int t) {
    int row = t >> 1, seg = t & 1;
    *(uint4*)(S + row * SM_STRIDE + seg * 16) = v[0];
    *(uint4*)(S + row * SM_STRIDE + seg * 16 + 8) = v[1];
}

// one 32-wide K chunk; aH/aL/bH/bL are per-lane ldmatrix base addresses
template<int MT, bool AHALF, int NB>
__device__ __forceinline__ void compute_chunk(float (&acc)[MT][4][4],
    uint32_t aH, uint32_t aL, uint32_t bH, uint32_t bL)
{
#pragma unroll
    for (int kk = 0; kk < 32; kk += 16) {
        uint32_t a[MT][4], bq[2][4];
#pragma unroll
        for (int i = 0; i < MT; i++) ldm_x4(a[i], aH + (i * 16 * SM_STRIDE + kk) * 2);
        ldm_x4(bq[0], bH + kk * 2);
        ldm_x4(bq[1], bH + (16 * SM_STRIDE + kk) * 2);
#pragma unroll
        for (int i = 0; i < MT; i++)
#pragma unroll
            for (int j = 0; j < 4; j++) {
                uint32_t bf[2] = { bq[j >> 1][j & 1], bq[j >> 1][2 + (j & 1)] };
                mma_16816(acc[i][j], a[i], bf);
            }
        if (NB == 2) {
            uint32_t blq[2][4];
            ldm_x4(blq[0], bL + kk * 2);
            ldm_x4(blq[1], bL + (16 * SM_STRIDE + kk) * 2);
#pragma unroll
            for (int i = 0; i < MT; i++)
#pragma unroll
                for (int j = 0; j < 4; j++) {
                    uint32_t bf[2] = { blq[j >> 1][j & 1], blq[j >> 1][2 + (j & 1)] };
                    mma_16816(acc[i][j], a[i], bf);
                }
        }
        if (!AHALF) {
            uint32_t al[MT][4];
#pragma unroll
            for (int i = 0; i < MT; i++) ldm_x4(al[i], aL + (i * 16 * SM_STRIDE + kk) * 2);
#pragma unroll
            for (int i = 0; i < MT; i++)
#pragma unroll
                for (int j = 0; j < 4; j++) {
                    uint32_t bf[2] = { bq[j >> 1][j & 1], bq[j >> 1][2 + (j & 1)] };
                    mma_16816(acc[i][j], al[i], bf);
                }
        }
    }
}

// ---------------------------------------------------------------------------
// HMMA GEMM: C[M,N] = A[M,K] @ B^T; B given as fp16 hi/lo planes [N][K].
// kcap>0: K truncated to min(K, m0+kcap) (mask-aware P·V).
// ---------------------------------------------------------------------------
template<int BN, int MT, bool AHALF, int NB>
__global__ void __launch_bounds__(256) hmma_gemm(
    const void* Av, int lda, long long aB,
    const __half* Bh, const __half* Bl, int ldb, long long bB,
    const float* __restrict__ bias, const float* __restrict__ res, int ldres,
    float* C, int ldc, long long cB, int K, int act, int kcap)
{
    constexpr int WARPS_M = 128 / (MT * 16);
    constexpr int ASZ = 128 * SM_STRIDE;
    constexpr int BSZ = BN * SM_STRIDE;
    __shared__ __align__(16) __half As[(AHALF ? 1 : 2) * ASZ];
    __shared__ __align__(16) __half Bs[NB * BSZ];

    int t = threadIdx.x, w = t >> 5, lane = t & 31;
    int warpY = w % WARPS_M, warpX = w / WARPS_M;
    int wm0 = warpY * MT * 16, wn0 = warpX * 32;
    int m0 = blockIdx.y * 128, n0 = blockIdx.x * BN;
    long long z = blockIdx.z;
    const float* Af = AHALF ? nullptr : (const float*)Av + z * aB;
    const __half* Ah = AHALF ? (const __half*)Av + z * aB : nullptr;
    const __half* BhZ = Bh + z * bB;
    const __half* BlZ = Bl + z * bB;
    float* Cz = C + z * cB;

    int loff = ((lane & 7) + ((lane >> 3) & 1) * 8) * SM_STRIDE + (lane >> 4) * 8;
    uint32_t aHa = smem_u32(As) + (wm0 * SM_STRIDE + loff) * 2;
    uint32_t aLa = aHa + ASZ * 2;
    uint32_t bHa = smem_u32(Bs) + (wn0 * SM_STRIDE + loff) * 2;
    uint32_t bLa = bHa + BSZ * 2;

    float acc[MT][4][4] = {};
    float4 va[4]; uint4 vah[2]; uint4 vbh[BN / 64], vbl[BN / 64];

    if (AHALF) ldg_h(vah, Ah, lda, m0, 0, t);
    else       ldg_f32<128>(va, Af, lda, m0, 0, t);
    ldg_h2<BN>(vbh, vbl, BhZ, BlZ, ldb, n0, 0, t);

    int KE = K;
    if (kcap) { KE = m0 + kcap; if (KE > K) KE = K; }
    int nch = KE >> 5;
    for (int c = 0; c < nch; c++) {
        if (AHALF) sts_h(vah, As, t);
        else       sts_hilo<128>(va, As, As + ASZ, t);
        sts_h2<BN>(vbh, vbl, Bs, Bs + BSZ, t);
        __syncthreads();
        if (c + 1 < nch) {
            int k0 = (c + 1) << 5;
            if (AHALF) ldg_h(vah, Ah, lda, m0, k0, t);
            else       ldg_f32<128>(va, Af, lda, m0, k0, t);
            ldg_h2<BN>(vbh, vbl, BhZ, BlZ, ldb, n0, k0, t);
        }
        compute_chunk<MT, AHALF, NB>(acc, aHa, aLa, bHa, bLa);
        __syncthreads();
    }

    int rb = m0 + wm0 + (lane >> 2);
    int cb = n0 + wn0 + ((lane & 3) << 1);
#pragma unroll
    for (int i = 0; i < MT; i++) {
#pragma unroll
        for (int j = 0; j < 4; j++) {
            int cc = cb + j * 8;
            float b0 = bias ? bias[cc] : 0.f, b1 = bias ? bias[cc + 1] : 0.f;
#pragma unroll
            for (int h = 0; h < 2; h++) {
                int r = rb + i * 16 + h * 8;
                float v0 = acc[i][j][2 * h] + b0;
                float v1 = acc[i][j][2 * h + 1] + b1;
                if (act) { v0 = gelu_new(v0); v1 = gelu_new(v1); }
                if (res) {
                    const float* rp = res + (long long)r * ldres + cc;
                    v0 += rp[0]; v1 += rp[1];
                }
                *(float2*)&Cz[(long long)r * ldc + cc] = make_float2(v0, v1);
            }
        }
    }
}

// ---------------------------------------------------------------------------
// Attention logits: 128q x 128k tile per CTA, inner K = 64. Fully-masked
// tiles early-out (softmax never reads past its q-tile cap).
// ---------------------------------------------------------------------------
__global__ void __launch_bounds__(256) hmma_scores(
    const float* Q, int ldq, const float* Km, int ldk,
    const float* __restrict__ kbias, float* __restrict__ Sout, int mode)
{
    int q0 = blockIdx.y * 128, k0 = blockIdx.x * 128;
    if (mode == 0) { if (k0 > q0) return; }
    else           { if (k0 > q0 + 128) return; }

    constexpr int ASZ = 128 * SM_STRIDE;
    __shared__ __align__(16) __half As[2 * ASZ];
    __shared__ __align__(16) __half Bs[2 * ASZ];

    int t = threadIdx.x, w = t >> 5, lane = t & 31;
    int warpY = w & 1, warpX = w >> 1;
    int wm0 = warpY * 64, wn0 = warpX * 32;
    int h = blockIdx.z;
    const float* Qg = Q + h * HEADD;
    const float* Kg = Km + h * HEADD;

    int loff = ((lane & 7) + ((lane >> 3) & 1) * 8) * SM_STRIDE + (lane >> 4) * 8;
    uint32_t aHa = smem_u32(As) + (wm0 * SM_STRIDE + loff) * 2;
    uint32_t aLa = aHa + ASZ * 2;
    uint32_t bHa = smem_u32(Bs) + (wn0 * SM_STRIDE + loff) * 2;
    uint32_t bLa = bHa + ASZ * 2;

    float acc[4][4][4] = {};
    float4 va[4], vb[4];

    ldg_f32<128>(va, Qg, ldq, q0, 0, t);
    ldg_f32<128>(vb, Kg, ldk, k0, 0, t);
#pragma unroll
    for (int c = 0; c < 2; c++) {
        sts_hilo<128>(va, As, As + ASZ, t);
        sts_hilo<128>(vb, Bs, Bs + ASZ, t);
        __syncthreads();
        if (c == 0) {
            ldg_f32<128>(va, Qg, ldq, q0, 32, t);
            ldg_f32<128>(vb, Kg, ldk, k0, 32, t);
        }
        compute_chunk<4, false, 2>(acc, aHa, aLa, bHa, bLa);
        __syncthreads();
    }

    int rb = q0 + wm0 + (lane >> 2);
    int cb = k0 + wn0 + ((lane & 3) << 1);
#pragma unroll
    for (int i = 0; i < 4; i++) {
#pragma unroll
        for (int j = 0; j < 4; j++) {
            int cc = cb + j * 8;
#pragma unroll
            for (int hh = 0; hh < 2; hh++) {
                int q = rb + i * 16 + hh * 8;
                float v0 = acc[i][j][2 * hh] * 0.125f;
                float v1 = acc[i][j][2 * hh + 1] * 0.125f;
                bool ok0, ok1;
                if (mode == 0) { ok0 = (cc <= q); ok1 = (cc + 1 <= q); }
                else {
                    v0 += kbias[cc]; v1 += kbias[cc + 1];
                    ok0 = (cc <= q + 2); ok1 = (cc + 1 <= q + 2);
                }
                float2 o = make_float2(ok0 ? v0 : -1e30f, ok1 ? v1 : -1e30f);
                *(float2*)&Sout[((long long)h * S_LEN + q) * S_LEN + cc] = o;
            }
        }
    }
}

// ---------------------------------------------------------------------------
__global__ void ln_kernel(const float* __restrict__ X, const float* __restrict__ g,
                          const float* __restrict__ b, float* __restrict__ Y)
{
    const float* x = X + (long long)blockIdx.x * H_DIM;
    float* y = Y + (long long)blockIdx.x * H_DIM;
    int tid = threadIdx.x;
    float v[4], s = 0.f, ss = 0.f;
#pragma unroll
    for (int i = 0; i < 4; i++) { v[i] = x[tid + i * 256]; s += v[i]; ss += v[i] * v[i]; }
    __shared__ float r1[256], r2[256];
    r1[tid] = s; r2[tid] = ss;
    __syncthreads();
#pragma unroll
    for (int st = 128; st >= 1; st >>= 1) {
        if (tid < st) { r1[tid] += r1[tid + st]; r2[tid] += r2[tid + st]; }
        __syncthreads();
    }
    float mean = r1[0] * (1.0f / H_DIM);
    float inv = rsqrtf(r2[0] * (1.0f / H_DIM) - mean * mean + 1e-5f);
#pragma unroll
    for (int i = 0; i < 4; i++) {
        int c = tid + i * 256;
        y[c] = (v[i] - mean) * inv * g[c] + b[c];
    }
}

// variable-length softmax: row q scans only [0, KP) where KP covers its
// q-tile's P·V read range; masked tail written as exact zeros.
__global__ void softmax_kernel(const float* __restrict__ S, __half* __restrict__ P, int mode)
{
    int r = blockIdx.x;
    int q = r & (S_LEN - 1);
    const float* row = S + (long long)r * S_LEN;
    __half* prow = P + (long long)r * S_LEN;
    int tid = threadIdx.x;
    int L = q + (mode == 0 ? 1 : 3); if (L > S_LEN) L = S_LEN;
    int q0 = q & ~127;
    int KP = (mode == 0) ? (q0 + 128) : (q0 + 160 > S_LEN ? S_LEN : q0 + 160);
    int nv = (KP + 255) >> 8;

    float vals[8], mx = -3.4e38f;
    for (int i = 0; i < nv; i++) {
        int idx = tid + (i << 8);
        float v = (idx < L) ? row[idx] : -1e30f;
        vals[i] = v; mx = fmaxf(mx, v);
    }
    __shared__ float red[256];
    red[tid] = mx; __syncthreads();
#pragma unroll
    for (int st = 128; st >= 1; st >>= 1) {
        if (tid < st) red[tid] = fmaxf(red[tid], red[tid + st]);
        __syncthreads();
    }
    mx = red[0]; __syncthreads();
    float sum = 0.f;
    for (int i = 0; i < nv; i++) { vals[i] = __expf(vals[i] - mx); sum += vals[i]; }
    red[tid] = sum; __syncthreads();
#pragma unroll
    for (int st = 128; st >= 1; st >>= 1) {
        if (tid < st) red[tid] += red[tid + st];
        __syncthreads();
    }
    float inv = 1.0f / red[0];
    for (int i = 0; i < nv; i++)
        prow[tid + (i << 8)] = __float2half_rn(vals[i] * inv);
}

// transpose fp32 [r][c] -> fp16 hi/lo planes [c][r]
__global__ void transpose_hilo(const float* __restrict__ in, int ldi,
                               __half* __restrict__ hi, __half* __restrict__ lo, int ldo)
{
    __shared__ float tbuf[32][33];
    int r0 = blockIdx.y * 32, c0 = blockIdx.x * 32;
    int tx = threadIdx.x, ty = threadIdx.y;
#pragma unroll
    for (int i = 0; i < 4; i++)
        tbuf[ty + i * 8][tx] = in[(long long)(r0 + ty + i * 8) * ldi + c0 + tx];
    __syncthreads();
#pragma unroll
    for (int i = 0; i < 4; i++) {
        float v = tbuf[tx][ty + i * 8];
        __half h = __float2half_rn(v);
        long long o = (long long)(c0 + ty + i * 8) * ldo + r0 + tx;
        hi[o] = h;
        lo[o] = __float2half_rn(v - __half2float(h));
    }
}

// ---------------------------------------------------------------------------
extern "C" void kernel_launch(void* const* d_in, const int* in_sizes, int n_in,
                              void* d_out, int out_size)
{
    const float* hidden = (const float*)d_in[0];
    const float* enc    = (const float*)d_in[1];
    const float* scorer = (const float*)d_in[2];
    const float* ln1_g = (const float*)d_in[3],  *ln1_b = (const float*)d_in[4];
    const float* c_attn_w = (const float*)d_in[5], *c_attn_b = (const float*)d_in[6];
    const float* attn_proj_w = (const float*)d_in[7], *attn_proj_b = (const float*)d_in[8];
    const float* lnx_g = (const float*)d_in[9],  *lnx_b = (const float*)d_in[10];
    const float* q_attn_w = (const float*)d_in[11], *q_attn_b = (const float*)d_in[12];
    const float* x_kv_w = (const float*)d_in[13], *x_kv_b = (const float*)d_in[14];
    const float* x_proj_w = (const float*)d_in[15], *x_proj_b = (const float*)d_in[16];
    const float* ln2_g = (const float*)d_in[17], *ln2_b = (const float*)d_in[18];
    const float* fc_w = (const float*)d_in[19], *fc_b = (const float*)d_in[20];
    const float* mlp_proj_w = (const float*)d_in[21], *mlp_proj_b = (const float*)d_in[22];
    float* out = (float*)d_out;

    float *x, *qkv, *scores, *attn, *hid2, *hid3, *qb, *kv, *mlp;
    __half *P, *wh, *vth;
    cudaGetSymbolAddress((void**)&x, g_x);
    cudaGetSymbolAddress((void**)&qkv, g_qkv);
    cudaGetSymbolAddress((void**)&scores, g_scores);
    cudaGetSymbolAddress((void**)&P, g_P);
    cudaGetSymbolAddress((void**)&attn, g_attn);
    cudaGetSymbolAddress((void**)&hid2, g_hid2);
    cudaGetSymbolAddress((void**)&hid3, g_hid3);
    cudaGetSymbolAddress((void**)&qb, g_q);
    cudaGetSymbolAddress((void**)&kv, g_kv);
    cudaGetSymbolAddress((void**)&mlp, g_mlp);
    cudaGetSymbolAddress((void**)&wh, g_wh);
    cudaGetSymbolAddress((void**)&vth, g_vth);

    dim3 tb(32, 8);
    const long long SS = (long long)S_LEN * S_LEN;

    // weights -> fp16 hi/lo planes [N][K]
    transpose_hilo<<<dim3(96, 32), tb>>>(c_attn_w, 3072, wh + WH_CA, wh + WH_CA + SZ_CA, 1024);
    transpose_hilo<<<dim3(32, 32), tb>>>(attn_proj_w, 1024, wh + WH_AP, wh + WH_AP + SZ_AP, 1024);
    transpose_hilo<<<dim3(32, 32), tb>>>(q_attn_w, 1024, wh + WH_QA, wh + WH_QA + SZ_QA, 1024);
    transpose_hilo<<<dim3(64, 32), tb>>>(x_kv_w, 2048, wh + WH_XKV, wh + WH_XKV + SZ_XKV, 1024);
    transpose_hilo<<<dim3(32, 32), tb>>>(x_proj_w, 1024, wh + WH_XP, wh + WH_XP + SZ_XP, 1024);
    transpose_hilo<<<dim3(128, 32), tb>>>(fc_w, 4096, wh + WH_FC, wh + WH_FC + SZ_FC, 1024);
    transpose_hilo<<<dim3(32, 128), tb>>>(mlp_proj_w, 1024, wh + WH_MP, wh + WH_MP + SZ_MP, 4096);

    // ---- self attention ----
    ln_kernel<<<S_LEN, 256>>>(hidden, ln1_g, ln1_b, x);
    hmma_gemm<128, 4, false, 2><<<dim3(24, 16, 1), 256>>>(x, 1024, 0,
        wh + WH_CA, wh + WH_CA + SZ_CA, 1024, 0,
        c_attn_b, nullptr, 0, qkv, 3072, 0, 1024, 0, 0);
    transpose_hilo<<<dim3(32, 64), tb>>>(qkv + 2048, 3072, vth, vth + VT_PLANE, 2048);  // V^T
    hmma_scores<<<dim3(16, 16, NHEAD), 256>>>(qkv, 3072, qkv + 1024, 3072,
        nullptr, scores, 0);
    softmax_kernel<<<NHEAD * S_LEN, 256>>>(scores, P, 0);
    hmma_gemm<64, 2, true, 2><<<dim3(1, 16, NHEAD), 256>>>(P, 2048, SS,
        vth, vth + VT_PLANE, 2048, (long long)64 * 2048,
        nullptr, nullptr, 0, attn, 1024, 64, 2048, 0, 128);
    hmma_gemm<128, 4, false, 2><<<dim3(8, 16, 1), 256>>>(attn, 1024, 0,
        wh + WH_AP, wh + WH_AP + SZ_AP, 1024, 0,
        attn_proj_b, hidden, 1024, hid2, 1024, 0, 1024, 0, 0);

    // ---- cross attention ----
    ln_kernel<<<S_LEN, 256>>>(hid2, lnx_g, lnx_b, x);
    hmma_gemm<128, 4, false, 2><<<dim3(8, 16, 1), 256>>>(x, 1024, 0,
        wh + WH_QA, wh + WH_QA + SZ_QA, 1024, 0,
        q_attn_b, nullptr, 0, qb, 1024, 0, 1024, 0, 0);
    hmma_gemm<128, 4, false, 2><<<dim3(16, 16, 1), 256>>>(enc, 1024, 0,
        wh + WH_XKV, wh + WH_XKV + SZ_XKV, 1024, 0,
        x_kv_b, nullptr, 0, kv, 2048, 0, 1024, 0, 0);
    transpose_hilo<<<dim3(32, 64), tb>>>(kv + 1024, 2048, vth, vth + VT_PLANE, 2048);   // V^T
    hmma_scores<<<dim3(16, 16, NHEAD), 256>>>(qb, 1024, kv, 2048,
        scorer, scores, 1);
    softmax_kernel<<<NHEAD * S_LEN, 256>>>(scores, P, 1);
    hmma_gemm<64, 2, true, 2><<<dim3(1, 16, NHEAD), 256>>>(P, 2048, SS,
        vth, vth + VT_PLANE, 2048, (long long)64 * 2048,
        nullptr, nullptr, 0, attn, 1024, 64, 2048, 0, 160);
    hmma_gemm<128, 4, false, 2><<<dim3(8, 16, 1), 256>>>(attn, 1024, 0,
        wh + WH_XP, wh + WH_XP + SZ_XP, 1024, 0,
        x_proj_b, hid2, 1024, hid3, 1024, 0, 1024, 0, 0);

    // ---- MLP ----
    ln_kernel<<<S_LEN, 256>>>(hid3, ln2_g, ln2_b, x);
    hmma_gemm<128, 4, false, 2><<<dim3(32, 16, 1), 256>>>(x, 1024, 0,
        wh + WH_FC, wh + WH_FC + SZ_FC, 1024, 0,
        fc_b, nullptr, 0, mlp, 4096, 0, 1024, 1, 0);
    hmma_gemm<128, 4, false, 2><<<dim3(8, 16, 1), 256>>>(mlp, 4096, 0,
        wh + WH_MP, wh + WH_MP + SZ_MP, 4096, 0,
        mlp_proj_b, hid3, 1024, out, 1024, 0, 4096, 0, 0);
}

// round 11
// speedup vs baseline: 3.2844x; 1.2615x over previous
#include <cuda_runtime.h>
#include <cuda_fp16.h>
#include <stdint.h>
#include <math.h>

#define S_LEN 2048
#define H_DIM 1024
#define NHEAD 16
#define HEADD 64
#define INNER_DIM 4096

// ---------------- scratch ----------------
__device__ float  g_x[S_LEN * H_DIM];
__device__ float  g_qkv[S_LEN * 3 * H_DIM];
__device__ float  g_attn[S_LEN * H_DIM];
__device__ float  g_hid2[S_LEN * H_DIM];
__device__ float  g_hid3[S_LEN * H_DIM];
__device__ float  g_q[S_LEN * H_DIM];
__device__ float  g_kv[S_LEN * 2 * H_DIM];
__device__ float  g_mlp[S_LEN * INNER_DIM];
__device__ __half g_wh[33554432];     // weights: hi plane then lo plane per weight
__device__ __half g_fh[12582912];     // per-head Q/K/V hi+lo planes (6 x 2M halves)

#define WH_CA  0
#define WH_AP  6291456
#define WH_QA  8388608
#define WH_XKV 10485760
#define WH_XP  14680064
#define WH_FC  16777216
#define WH_MP  25165824
#define SZ_CA  3145728
#define SZ_AP  1048576
#define SZ_QA  1048576
#define SZ_XKV 2097152
#define SZ_XP  1048576
#define SZ_FC  4194304
#define SZ_MP  4194304
#define FH_PL  2097152   // one plane: 16 heads x 2048 x 64

#define SM_STRIDE 40   // dense-GEMM smem stride (32 data + 8 pad)

__device__ __forceinline__ float gelu_new(float x) {
    const float c = 0.7978845608028654f;
    return 0.5f * x * (1.0f + tanhf(c * (x + 0.044715f * x * x * x)));
}
__device__ __forceinline__ uint32_t smem_u32(const void* p) {
    uint32_t a;
    asm("{ .reg .u64 t; cvta.to.shared.u64 t, %1; cvt.u32.u64 %0, t; }" : "=r"(a) : "l"(p));
    return a;
}

// ---- HMMA m16n8k16 f16f16f32 + ldmatrix ----
__device__ __forceinline__ void mma_16816(float c[4], const uint32_t a[4], const uint32_t b[2]) {
    asm volatile("mma.sync.aligned.m16n8k16.row.col.f32.f16.f16.f32 "
        "{%0,%1,%2,%3}, {%4,%5,%6,%7}, {%8,%9}, {%0,%1,%2,%3};"
        : "+f"(c[0]), "+f"(c[1]), "+f"(c[2]), "+f"(c[3])
        : "r"(a[0]), "r"(a[1]), "r"(a[2]), "r"(a[3]), "r"(b[0]), "r"(b[1]));
}
__device__ __forceinline__ void ldm_x4(uint32_t r[4], uint32_t addr) {
    asm volatile("ldmatrix.sync.aligned.m8n8.x4.shared.b16 {%0,%1,%2,%3}, [%4];"
        : "=r"(r[0]), "=r"(r[1]), "=r"(r[2]), "=r"(r[3]) : "r"(addr));
}
__device__ __forceinline__ void ldm_x4_t(uint32_t r[4], uint32_t addr) {
    asm volatile("ldmatrix.sync.aligned.m8n8.x4.trans.shared.b16 {%0,%1,%2,%3}, [%4];"
        : "=r"(r[0]), "=r"(r[1]), "=r"(r[2]), "=r"(r[3]) : "r"(addr));
}

// ================= dense GEMM machinery (unchanged, known-good) ============
template<int R>
__device__ __forceinline__ void ldg_f32(float4 (&v)[R / 32], const float* A, int lda,
                                        int row0, int k0, int t) {
    constexpr int TPR = 256 / R;
    constexpr int FPT = R / 8;
    int row = t / TPR, seg = t % TPR;
    const float* p = A + (long long)(row0 + row) * lda + k0 + seg * FPT;
#pragma unroll
    for (int i = 0; i < R / 32; i++) v[i] = *(const float4*)(p + i * 4);
}
template<int R>
__device__ __forceinline__ void sts_hilo(const float4 (&v)[R / 32], __half* hi, __half* lo, int t) {
    constexpr int TPR = 256 / R;
    constexpr int FPT = R / 8;
    int row = t / TPR, seg = t % TPR;
    __half2* ph = (__half2*)(hi + row * SM_STRIDE + seg * FPT);
    __half2* pl = (__half2*)(lo + row * SM_STRIDE + seg * FPT);
    const float* f = (const float*)v;
#pragma unroll
    for (int i = 0; i < FPT / 2; i++) {
        __half h0 = __float2half_rn(f[2 * i]), h1 = __float2half_rn(f[2 * i + 1]);
        ph[i] = __halves2half2(h0, h1);
        pl[i] = __halves2half2(__float2half_rn(f[2 * i] - __half2float(h0)),
                               __float2half_rn(f[2 * i + 1] - __half2float(h1)));
    }
}
template<int R>
__device__ __forceinline__ void ldg_h2(uint4 (&vh)[R / 64], uint4 (&vl)[R / 64],
                                       const __half* Bh, const __half* Bl,
                                       int ldb, int n0, int k0, int t) {
    constexpr int TPR = 256 / R;
    constexpr int HPT = 32 / TPR;
    int row = t / TPR, seg = t % TPR;
    const __half* ph = Bh + (long long)(n0 + row) * ldb + k0 + seg * HPT;
    const __half* pl = Bl + (long long)(n0 + row) * ldb + k0 + seg * HPT;
#pragma unroll
    for (int u = 0; u < R / 64; u++) { vh[u] = ((const uint4*)ph)[u]; vl[u] = ((const uint4*)pl)[u]; }
}
template<int R>
__device__ __forceinline__ void sts_h2(const uint4 (&vh)[R / 64], const uint4 (&vl)[R / 64],
                                       __half* hi, __half* lo, int t) {
    constexpr int TPR = 256 / R;
    constexpr int HPT = 32 / TPR;
    int row = t / TPR, seg = t % TPR;
    __half* ph = hi + row * SM_STRIDE + seg * HPT;
    __half* pl = lo + row * SM_STRIDE + seg * HPT;
#pragma unroll
    for (int u = 0; u < R / 64; u++) { ((uint4*)ph)[u] = vh[u]; ((uint4*)pl)[u] = vl[u]; }
}
template<int MT, bool AHALF, int NB>
__device__ __forceinline__ void compute_chunk(float (&acc)[MT][4][4],
    uint32_t aH, uint32_t aL, uint32_t bH, uint32_t bL)
{
#pragma unroll
    for (int kk = 0; kk < 32; kk += 16) {
        uint32_t a[MT][4], bq[2][4];
#pragma unroll
        for (int i = 0; i < MT; i++) ldm_x4(a[i], aH + (i * 16 * SM_STRIDE + kk) * 2);
        ldm_x4(bq[0], bH + kk * 2);
        ldm_x4(bq[1], bH + (16 * SM_STRIDE + kk) * 2);
#pragma unroll
        for (int i = 0; i < MT; i++)
#pragma unroll
            for (int j = 0; j < 4; j++) {
                uint32_t bf[2] = { bq[j >> 1][j & 1], bq[j >> 1][2 + (j & 1)] };
                mma_16816(acc[i][j], a[i], bf);
            }
        if (NB == 2) {
            uint32_t blq[2][4];
            ldm_x4(blq[0], bL + kk * 2);
            ldm_x4(blq[1], bL + (16 * SM_STRIDE + kk) * 2);
#pragma unroll
            for (int i = 0; i < MT; i++)
#pragma unroll
                for (int j = 0; j < 4; j++) {
                    uint32_t bf[2] = { blq[j >> 1][j & 1], blq[j >> 1][2 + (j & 1)] };
                    mma_16816(acc[i][j], a[i], bf);
                }
        }
        if (!AHALF) {
            uint32_t al[MT][4];
#pragma unroll
            for (int i = 0; i < MT; i++) ldm_x4(al[i], aL + (i * 16 * SM_STRIDE + kk) * 2);
#pragma unroll
            for (int i = 0; i < MT; i++)
#pragma unroll
                for (int j = 0; j < 4; j++) {
                    uint32_t bf[2] = { bq[j >> 1][j & 1], bq[j >> 1][2 + (j & 1)] };
                    mma_16816(acc[i][j], al[i], bf);
                }
        }
    }
}

template<int BN, int MT, bool AHALF, int NB>
__global__ void __launch_bounds__(256) hmma_gemm(
    const void* Av, int lda, long long aB,
    const __half* Bh, const __half* Bl, int ldb, long long bB,
    const float* __restrict__ bias, const float* __restrict__ res, int ldres,
    float* C, int ldc, long long cB, int K, int act)
{
    constexpr int WARPS_M = 128 / (MT * 16);
    constexpr int ASZ = 128 * SM_STRIDE;
    constexpr int BSZ = BN * SM_STRIDE;
    __shared__ __align__(16) __half As[2 * ASZ];
    __shared__ __align__(16) __half Bs[NB * BSZ];

    int t = threadIdx.x, w = t >> 5, lane = t & 31;
    int warpY = w % WARPS_M, warpX = w / WARPS_M;
    int wm0 = warpY * MT * 16, wn0 = warpX * 32;
    int m0 = blockIdx.y * 128, n0 = blockIdx.x * BN;
    long long z = blockIdx.z;
    const float* Af = (const float*)Av + z * aB;
    const __half* BhZ = Bh + z * bB;
    const __half* BlZ = Bl + z * bB;
    float* Cz = C + z * cB;

    int loff = ((lane & 7) + ((lane >> 3) & 1) * 8) * SM_STRIDE + (lane >> 4) * 8;
    uint32_t aHa = smem_u32(As) + (wm0 * SM_STRIDE + loff) * 2;
    uint32_t aLa = aHa + ASZ * 2;
    uint32_t bHa = smem_u32(Bs) + (wn0 * SM_STRIDE + loff) * 2;
    uint32_t bLa = bHa + BSZ * 2;

    float acc[MT][4][4] = {};
    float4 va[4]; uint4 vbh[BN / 64], vbl[BN / 64];

    ldg_f32<128>(va, Af, lda, m0, 0, t);
    ldg_h2<BN>(vbh, vbl, BhZ, BlZ, ldb, n0, 0, t);

    int nch = K >> 5;
    for (int c = 0; c < nch; c++) {
        sts_hilo<128>(va, As, As + ASZ, t);
        sts_h2<BN>(vbh, vbl, Bs, Bs + BSZ, t);
        __syncthreads();
        if (c + 1 < nch) {
            int k0 = (c + 1) << 5;
            ldg_f32<128>(va, Af, lda, m0, k0, t);
            ldg_h2<BN>(vbh, vbl, BhZ, BlZ, ldb, n0, k0, t);
        }
        compute_chunk<MT, AHALF, NB>(acc, aHa, aLa, bHa, bLa);
        __syncthreads();
    }

    int rb = m0 + wm0 + (lane >> 2);
    int cb = n0 + wn0 + ((lane & 3) << 1);
#pragma unroll
    for (int i = 0; i < MT; i++) {
#pragma unroll
        for (int j = 0; j < 4; j++) {
            int cc = cb + j * 8;
            float b0 = bias ? bias[cc] : 0.f, b1 = bias ? bias[cc + 1] : 0.f;
#pragma unroll
            for (int h = 0; h < 2; h++) {
                int r = rb + i * 16 + h * 8;
                float v0 = acc[i][j][2 * h] + b0;
                float v1 = acc[i][j][2 * h + 1] + b1;
                if (act) { v0 = gelu_new(v0); v1 = gelu_new(v1); }
                if (res) {
                    const float* rp = res + (long long)r * ldres + cc;
                    v0 += rp[0]; v1 += rp[1];
                }
                *(float2*)&Cz[(long long)r * ldc + cc] = make_float2(v0, v1);
            }
        }
    }
}

// ================= fused flash attention ===================================
// Q/K/V given as per-head fp16 hi/lo planes [h][S][64]. One CTA = (q-tile 128,
// head). 8 warps, warp w owns q-rows 16w..16w+15 and the full 128-wide k-block.
// Online softmax in registers; P (fp16) feeds P.V directly from C-fragments.
// mode 0: causal; mode 1: k<=q+2 + scorer bias.
__global__ void __launch_bounds__(256) flash_attn(
    const __half* __restrict__ QH, const __half* __restrict__ QL,
    const __half* __restrict__ KH, const __half* __restrict__ KL,
    const __half* __restrict__ VH, const __half* __restrict__ VL,
    const float* __restrict__ kbias, float* __restrict__ O, int mode)
{
    constexpr int ST = 72;          // 64 data + 8 pad: conflict-free ldmatrix
    constexpr int PL = 128 * ST;
    extern __shared__ __half sm[];
    __half* sQh = sm;
    __half* sKh = sm + 2 * PL;
    __half* sVh = sm + 4 * PL;

    int t = threadIdx.x, w = t >> 5, lane = t & 31;
    int qt = gridDim.x - 1 - blockIdx.x;   // heavy tiles first
    int h = blockIdx.y;
    int m0 = qt * 128;
    size_t hb = (size_t)h * S_LEN * 64;

    {   // Q tile -> smem (hi, lo)
        int row = t >> 1, seg = (t & 1) * 32;
        size_t g = hb + (size_t)(m0 + row) * 64 + seg;
        uint4* dh = (uint4*)(sQh + row * ST + seg);
        uint4* dl = (uint4*)(sQh + PL + row * ST + seg);
#pragma unroll
        for (int u = 0; u < 4; u++) {
            dh[u] = ((const uint4*)(QH + g))[u];
            dl[u] = ((const uint4*)(QL + g))[u];
        }
    }

    int wr = w * 16;
    int krow = (lane & 7) + ((lane >> 3) & 1) * 8;
    int chi = (lane >> 4) * 8;
    uint32_t aQh = smem_u32(sQh) + ((wr + krow) * ST + chi) * 2;
    uint32_t aK = smem_u32(sKh) + (krow * ST + chi) * 2;
    uint32_t aV = smem_u32(sVh) + (krow * ST + chi) * 2;

    float mrow0 = -1e30f, mrow1 = -1e30f, l0 = 0.f, l1 = 0.f;
    float o[8][4] = {};
    int r_lo = m0 + wr + (lane >> 2);
    int cbase = 2 * (lane & 3);

    int nkb = (mode == 0) ? (qt + 1) : min(16, qt + 2);
    for (int kb = 0; kb < nkb; kb++) {
        __syncthreads();
        {   // K,V tiles -> smem
            int row = t >> 1, seg = (t & 1) * 32;
            size_t g = hb + (size_t)(kb * 128 + row) * 64 + seg;
            uint4* d0 = (uint4*)(sKh + row * ST + seg);
            uint4* d1 = (uint4*)(sKh + PL + row * ST + seg);
            uint4* d2 = (uint4*)(sVh + row * ST + seg);
            uint4* d3 = (uint4*)(sVh + PL + row * ST + seg);
#pragma unroll
            for (int u = 0; u < 4; u++) {
                d0[u] = ((const uint4*)(KH + g))[u];
                d1[u] = ((const uint4*)(KL + g))[u];
                d2[u] = ((const uint4*)(VH + g))[u];
                d3[u] = ((const uint4*)(VL + g))[u];
            }
        }
        __syncthreads();

        // ---- S = Q K^T (hi*hi + hi*lo + lo*hi) ----
        float s[16][4] = {};
#pragma unroll
        for (int kk = 0; kk < 64; kk += 16) {
            uint32_t ah[4], al[4];
            ldm_x4(ah, aQh + kk * 2);
            ldm_x4(al, aQh + PL * 2 + kk * 2);
#pragma unroll
            for (int nb = 0; nb < 8; nb++) {
                uint32_t bh[4], bl[4];
                uint32_t off = (uint32_t)(nb * 16 * ST + kk) * 2;
                ldm_x4(bh, aK + off);
                ldm_x4(bl, aK + PL * 2 + off);
#pragma unroll
                for (int j = 0; j < 2; j++) {
                    uint32_t bfh[2] = { bh[j], bh[2 + j] };
                    uint32_t bfl[2] = { bl[j], bl[2 + j] };
                    mma_16816(s[nb * 2 + j], ah, bfh);
                    mma_16816(s[nb * 2 + j], ah, bfl);
                    mma_16816(s[nb * 2 + j], al, bfh);
                }
            }
        }

        // ---- scale + bias + mask; row max ----
        int k0c = kb * 128;
        float mx0 = mrow0, mx1 = mrow1;
        int lim0 = (mode == 0) ? r_lo : r_lo + 2;
        int lim1 = lim0 + 8;
#pragma unroll
        for (int nf = 0; nf < 16; nf++) {
            int c0 = k0c + nf * 8 + cbase;
            float b0 = (mode == 1) ? kbias[c0] : 0.f;
            float b1 = (mode == 1) ? kbias[c0 + 1] : 0.f;
            s[nf][0] = (c0 <= lim0)     ? s[nf][0] * 0.125f + b0 : -1e30f;
            s[nf][1] = (c0 + 1 <= lim0) ? s[nf][1] * 0.125f + b1 : -1e30f;
            s[nf][2] = (c0 <= lim1)     ? s[nf][2] * 0.125f + b0 : -1e30f;
            s[nf][3] = (c0 + 1 <= lim1) ? s[nf][3] * 0.125f + b1 : -1e30f;
            mx0 = fmaxf(mx0, fmaxf(s[nf][0], s[nf][1]));
            mx1 = fmaxf(mx1, fmaxf(s[nf][2], s[nf][3]));
        }
        mx0 = fmaxf(mx0, __shfl_xor_sync(0xffffffffu, mx0, 1));
        mx0 = fmaxf(mx0, __shfl_xor_sync(0xffffffffu, mx0, 2));
        mx1 = fmaxf(mx1, __shfl_xor_sync(0xffffffffu, mx1, 1));
        mx1 = fmaxf(mx1, __shfl_xor_sync(0xffffffffu, mx1, 2));
        float corr0 = __expf(mrow0 - mx0), corr1 = __expf(mrow1 - mx1);
        mrow0 = mx0; mrow1 = mx1;

        // ---- P = exp(S - m); row sums; pack to fp16 A-fragments ----
        float sum0 = 0.f, sum1 = 0.f;
        uint32_t p[16][2];
#pragma unroll
        for (int nf = 0; nf < 16; nf++) {
            float p0 = __expf(s[nf][0] - mx0), p1 = __expf(s[nf][1] - mx0);
            float p2 = __expf(s[nf][2] - mx1), p3 = __expf(s[nf][3] - mx1);
            sum0 += p0 + p1; sum1 += p2 + p3;
            __half2 h01 = __float22half2_rn(make_float2(p0, p1));
            __half2 h23 = __float22half2_rn(make_float2(p2, p3));
            p[nf][0] = *(uint32_t*)&h01;
            p[nf][1] = *(uint32_t*)&h23;
        }
        sum0 += __shfl_xor_sync(0xffffffffu, sum0, 1);
        sum0 += __shfl_xor_sync(0xffffffffu, sum0, 2);
        sum1 += __shfl_xor_sync(0xffffffffu, sum1, 1);
        sum1 += __shfl_xor_sync(0xffffffffu, sum1, 2);
        l0 = l0 * corr0 + sum0;
        l1 = l1 * corr1 + sum1;
#pragma unroll
        for (int df = 0; df < 8; df++) {
            o[df][0] *= corr0; o[df][1] *= corr0;
            o[df][2] *= corr1; o[df][3] *= corr1;
        }

        // ---- O += P V (V hi + lo via ldmatrix.trans) ----
#pragma unroll
        for (int kc = 0; kc < 8; kc++) {
            uint32_t a[4] = { p[2 * kc][0], p[2 * kc][1], p[2 * kc + 1][0], p[2 * kc + 1][1] };
#pragma unroll
            for (int dx = 0; dx < 4; dx++) {
                uint32_t bh[4], bl[4];
                uint32_t off = (uint32_t)(kc * 16 * ST + dx * 16) * 2;
                ldm_x4_t(bh, aV + off);
                ldm_x4_t(bl, aV + PL * 2 + off);
                uint32_t bf0[2] = { bh[0], bh[1] }, bf1[2] = { bh[2], bh[3] };
                uint32_t bg0[2] = { bl[0], bl[1] }, bg1[2] = { bl[2], bl[3] };
                mma_16816(o[dx * 2],     a, bf0);
                mma_16816(o[dx * 2 + 1], a, bf1);
                mma_16816(o[dx * 2],     a, bg0);
                mma_16816(o[dx * 2 + 1], a, bg1);
            }
        }
    }

    float inv0 = 1.f / l0, inv1 = 1.f / l1;
    int colb = h * 64 + cbase;
#pragma unroll
    for (int df = 0; df < 8; df++) {
        int cc = colb + df * 8;
        *(float2*)&O[(long long)r_lo * H_DIM + cc] =
            make_float2(o[df][0] * inv0, o[df][1] * inv0);
        *(float2*)&O[(long long)(r_lo + 8) * H_DIM + cc] =
            make_float2(o[df][2] * inv1, o[df][3] * inv1);
    }
}

// split fp32 [s][ld] (cols coloff..coloff+1023) into per-head fp16 hi/lo planes [h][s][64]
__global__ void split_hilo(const float* __restrict__ src, int ld, int coloff,
                           __half* __restrict__ hi, __half* __restrict__ lo)
{
    int s = blockIdx.x, t = threadIdx.x;
#pragma unroll
    for (int i = 0; i < 4; i++) {
        int c = t + i * 256;
        float v = src[(long long)s * ld + coloff + c];
        int hh = c >> 6, d = c & 63;
        __half hv = __float2half_rn(v);
        size_t o = ((size_t)hh * S_LEN + s) * 64 + d;
        hi[o] = hv;
        lo[o] = __float2half_rn(v - __half2float(hv));
    }
}

// ---------------------------------------------------------------------------
__global__ void ln_kernel(const float* __restrict__ X, const float* __restrict__ g,
                          const float* __restrict__ b, float* __restrict__ Y)
{
    const float* x = X + (long long)blockIdx.x * H_DIM;
    float* y = Y + (long long)blockIdx.x * H_DIM;
    int tid = threadIdx.x;
    float v[4], s = 0.f, ss = 0.f;
#pragma unroll
    for (int i = 0; i < 4; i++) { v[i] = x[tid + i * 256]; s += v[i]; ss += v[i] * v[i]; }
    __shared__ float r1[256], r2[256];
    r1[tid] = s; r2[tid] = ss;
    __syncthreads();
#pragma unroll
    for (int st = 128; st >= 1; st >>= 1) {
        if (tid < st) { r1[tid] += r1[tid + st]; r2[tid] += r2[tid + st]; }
        __syncthreads();
    }
    float mean = r1[0] * (1.0f / H_DIM);
    float inv = rsqrtf(r2[0] * (1.0f / H_DIM) - mean * mean + 1e-5f);
#pragma unroll
    for (int i = 0; i < 4; i++) {
        int c = tid + i * 256;
        y[c] = (v[i] - mean) * inv * g[c] + b[c];
    }
}

// transpose fp32 [r][c] -> fp16 hi/lo planes [c][r]  (weights only)
__global__ void transpose_hilo(const float* __restrict__ in, int ldi,
                               __half* __restrict__ hi, __half* __restrict__ lo, int ldo)
{
    __shared__ float tbuf[32][33];
    int r0 = blockIdx.y * 32, c0 = blockIdx.x * 32;
    int tx = threadIdx.x, ty = threadIdx.y;
#pragma unroll
    for (int i = 0; i < 4; i++)
        tbuf[ty + i * 8][tx] = in[(long long)(r0 + ty + i * 8) * ldi + c0 + tx];
    __syncthreads();
#pragma unroll
    for (int i = 0; i < 4; i++) {
        float v = tbuf[tx][ty + i * 8];
        __half h = __float2half_rn(v);
        long long o = (long long)(c0 + ty + i * 8) * ldo + r0 + tx;
        hi[o] = h;
        lo[o] = __float2half_rn(v - __half2float(h));
    }
}

// ---------------------------------------------------------------------------
extern "C" void kernel_launch(void* const* d_in, const int* in_sizes, int n_in,
                              void* d_out, int out_size)
{
    const float* hidden = (const float*)d_in[0];
    const float* enc    = (const float*)d_in[1];
    const float* scorer = (const float*)d_in[2];
    const float* ln1_g = (const float*)d_in[3],  *ln1_b = (const float*)d_in[4];
    const float* c_attn_w = (const float*)d_in[5], *c_attn_b = (const float*)d_in[6];
    const float* attn_proj_w = (const float*)d_in[7], *attn_proj_b = (const float*)d_in[8];
    const float* lnx_g = (const float*)d_in[9],  *lnx_b = (const float*)d_in[10];
    const float* q_attn_w = (const float*)d_in[11], *q_attn_b = (const float*)d_in[12];
    const float* x_kv_w = (const float*)d_in[13], *x_kv_b = (const float*)d_in[14];
    const float* x_proj_w = (const float*)d_in[15], *x_proj_b = (const float*)d_in[16];
    const float* ln2_g = (const float*)d_in[17], *ln2_b = (const float*)d_in[18];
    const float* fc_w = (const float*)d_in[19], *fc_b = (const float*)d_in[20];
    const float* mlp_proj_w = (const float*)d_in[21], *mlp_proj_b = (const float*)d_in[22];
    float* out = (float*)d_out;

    float *x, *qkv, *attn, *hid2, *hid3, *qb, *kv, *mlp;
    __half *wh, *fh;
    cudaGetSymbolAddress((void**)&x, g_x);
    cudaGetSymbolAddress((void**)&qkv, g_qkv);
    cudaGetSymbolAddress((void**)&attn, g_attn);
    cudaGetSymbolAddress((void**)&hid2, g_hid2);
    cudaGetSymbolAddress((void**)&hid3, g_hid3);
    cudaGetSymbolAddress((void**)&qb, g_q);
    cudaGetSymbolAddress((void**)&kv, g_kv);
    cudaGetSymbolAddress((void**)&mlp, g_mlp);
    cudaGetSymbolAddress((void**)&wh, g_wh);
    cudaGetSymbolAddress((void**)&fh, g_fh);

    __half *QH = fh,             *QL = fh + FH_PL;
    __half *KH = fh + 2 * FH_PL, *KL = fh + 3 * FH_PL;
    __half *VH = fh + 4 * FH_PL, *VL = fh + 5 * FH_PL;

    const int FSM = 6 * 128 * 72 * 2;   // 110592 bytes
    cudaFuncSetAttribute(flash_attn, cudaFuncAttributeMaxDynamicSharedMemorySize, FSM);

    dim3 tb(32, 8);

    // weights -> fp16 hi/lo planes [N][K]
    transpose_hilo<<<dim3(96, 32), tb>>>(c_attn_w, 3072, wh + WH_CA, wh + WH_CA + SZ_CA, 1024);
    transpose_hilo<<<dim3(32, 32), tb>>>(attn_proj_w, 1024, wh + WH_AP, wh + WH_AP + SZ_AP, 1024);
    transpose_hilo<<<dim3(32, 32), tb>>>(q_attn_w, 1024, wh + WH_QA, wh + WH_QA + SZ_QA, 1024);
    transpose_hilo<<<dim3(64, 32), tb>>>(x_kv_w, 2048, wh + WH_XKV, wh + WH_XKV + SZ_XKV, 1024);
    transpose_hilo<<<dim3(32, 32), tb>>>(x_proj_w, 1024, wh + WH_XP, wh + WH_XP + SZ_XP, 1024);
    transpose_hilo<<<dim3(128, 32), tb>>>(fc_w, 4096, wh + WH_FC, wh + WH_FC + SZ_FC, 1024);
    transpose_hilo<<<dim3(32, 128), tb>>>(mlp_proj_w, 1024, wh + WH_MP, wh + WH_MP + SZ_MP, 4096);

    // ---- self attention ----
    ln_kernel<<<S_LEN, 256>>>(hidden, ln1_g, ln1_b, x);
    hmma_gemm<128, 4, false, 2><<<dim3(24, 16, 1), 256>>>(x, 1024, 0,
        wh + WH_CA, wh + WH_CA + SZ_CA, 1024, 0,
        c_attn_b, nullptr, 0, qkv, 3072, 0, 1024, 0);
    split_hilo<<<S_LEN, 256>>>(qkv, 3072, 0, QH, QL);
    split_hilo<<<S_LEN, 256>>>(qkv, 3072, 1024, KH, KL);
    split_hilo<<<S_LEN, 256>>>(qkv, 3072, 2048, VH, VL);
    flash_attn<<<dim3(16, NHEAD), 256, FSM>>>(QH, QL, KH, KL, VH, VL, nullptr, attn, 0);
    hmma_gemm<128, 4, false, 2><<<dim3(8, 16, 1), 256>>>(attn, 1024, 0,
        wh + WH_AP, wh + WH_AP + SZ_AP, 1024, 0,
        attn_proj_b, hidden, 1024, hid2, 1024, 0, 1024, 0);

    // ---- cross attention ----
    ln_kernel<<<S_LEN, 256>>>(hid2, lnx_g, lnx_b, x);
    hmma_gemm<128, 4, false, 2><<<dim3(8, 16, 1), 256>>>(x, 1024, 0,
        wh + WH_QA, wh + WH_QA + SZ_QA, 1024, 0,
        q_attn_b, nullptr, 0, qb, 1024, 0, 1024, 0);
    hmma_gemm<128, 4, false, 2><<<dim3(16, 16, 1), 256>>>(enc, 1024, 0,
        wh + WH_XKV, wh + WH_XKV + SZ_XKV, 1024, 0,
        x_kv_b, nullptr, 0, kv, 2048, 0, 1024, 0);
    split_hilo<<<S_LEN, 256>>>(qb, 1024, 0, QH, QL);
    split_hilo<<<S_LEN, 256>>>(kv, 2048, 0, KH, KL);
    split_hilo<<<S_LEN, 256>>>(kv, 2048, 1024, VH, VL);
    flash_attn<<<dim3(16, NHEAD), 256, FSM>>>(QH, QL, KH, KL, VH, VL, scorer, attn, 1);
    hmma_gemm<128, 4, false, 2><<<dim3(8, 16, 1), 256>>>(attn, 1024, 0,
        wh + WH_XP, wh + WH_XP + SZ_XP, 1024, 0,
        x_proj_b, hid2, 1024, hid3, 1024, 0, 1024, 0);

    // ---- MLP ----
    ln_kernel<<<S_LEN, 256>>>(hid3, ln2_g, ln2_b, x);
    hmma_gemm<128, 4, false, 2><<<dim3(32, 16, 1), 256>>>(x, 1024, 0,
        wh + WH_FC, wh + WH_FC + SZ_FC, 1024, 0,
        fc_b, nullptr, 0, mlp, 4096, 0, 1024, 1);
    hmma_gemm<128, 4, false, 2><<<dim3(8, 16, 1), 256>>>(mlp, 4096, 0,
        wh + WH_MP, wh + WH_MP + SZ_MP, 4096, 0,
        mlp_proj_b, hid3, 1024, out, 1024, 0, 4096, 0);
}